// round 3
// baseline (speedup 1.0000x reference)
#include <cuda_runtime.h>
#include <cuda_bf16.h>
#include <cstdint>
#include <cstdio>

// ---------------- problem constants ----------------
#define NH   128        // hidden
#define NB   512        // graphs
#define NN   8192       // nodes
#define NE   16384      // edges
#define NED  32         // edge dim
#define HH   16384      // H*H

// ---------------- device scratch ----------------
__device__ float g_hmid[NE * NH];                       // 8 MB
__device__ float g_w2p[HH * NH];                        // 8 MB, [m=j*128+i][k]
__device__ float g_b2p[HH];
__device__ float g_T[(size_t)NE * HH];                  // 1 GiB, [e][j][i] fp32
__device__ float g_node[NN * NH];
__device__ float g_update[NN * NH];
__device__ float g_gi[NN * 3 * NH];
__device__ float g_gh[NN * 3 * NH];
__device__ float g_h[NB * NH];
__device__ float g_c[NB * NH];
__device__ float g_qstar[NB * 2 * NH];
__device__ float g_gl1[NB * 4 * NH];
__device__ float g_gl2[NB * 4 * NH];
__device__ float g_prod[NN];
__device__ unsigned int g_m[NB];
__device__ float g_d[NB];

// ---------------- helpers ----------------
__device__ __forceinline__ uint32_t f2tf(float f) {
    uint32_t u;
    asm("cvt.rna.tf32.f32 %0, %1;" : "=r"(u) : "f"(f));
    return u;
}

__device__ __forceinline__ void mma8(float* c, const uint32_t* a, const uint32_t* b) {
    asm volatile(
        "mma.sync.aligned.m16n8k8.row.col.f32.tf32.tf32.f32 "
        "{%0,%1,%2,%3},{%4,%5,%6,%7},{%8,%9},{%0,%1,%2,%3};"
        : "+f"(c[0]), "+f"(c[1]), "+f"(c[2]), "+f"(c[3])
        : "r"(a[0]), "r"(a[1]), "r"(a[2]), "r"(a[3]), "r"(b[0]), "r"(b[1]));
}

__device__ __forceinline__ float sigm(float x) { return 1.0f / (1.0f + expf(-x)); }

__device__ __forceinline__ unsigned int fkey(float f) {
    unsigned int b = __float_as_uint(f);
    return (b & 0x80000000u) ? ~b : (b | 0x80000000u);
}
__device__ __forceinline__ float fdekey(unsigned int k) {
    unsigned int b = (k & 0x80000000u) ? (k & 0x7fffffffu) : ~k;
    return __uint_as_float(b);
}

// ---------------- tf32 GEMM: C[M,N] = A[M,K] @ B[N,K]^T (+bias[n]) ----------------
// NS=1: single tf32 pass. NS=2: 3xTF32 split precision (~fp32 accuracy).
// M,N multiples of 128; K multiple of 32. 256 threads; warp tile 32x64.
template <int NS>
__global__ void gemm_tf32(const float* __restrict__ A, const float* __restrict__ B,
                          float* __restrict__ C, const float* __restrict__ bias,
                          int M, int N, int K) {
    extern __shared__ uint32_t sm[];
    uint32_t (*As)[128][36] = (uint32_t (*)[128][36])sm;
    uint32_t (*Bs)[128][36] = (uint32_t (*)[128][36])(sm + NS * 128 * 36);

    const int tid  = threadIdx.x;
    const int warp = tid >> 5, lane = tid & 31;
    const int grp  = lane >> 2, tig = lane & 3;
    const int wm   = warp & 3, wn = warp >> 2;
    const int m_cta = blockIdx.y * 128;
    const int n_cta = blockIdx.x * 128;

    float c[2][8][4] = {};

    const int lr = tid >> 3;
    const int lc = (tid & 7) * 4;

    for (int k0 = 0; k0 < K; k0 += 32) {
#pragma unroll
        for (int p = 0; p < 4; ++p) {
            int row = lr + p * 32;
            float4 va = *(const float4*)(A + (size_t)(m_cta + row) * K + k0 + lc);
            float4 vb = *(const float4*)(B + (size_t)(n_cta + row) * K + k0 + lc);
            uint32_t ah[4] = {f2tf(va.x), f2tf(va.y), f2tf(va.z), f2tf(va.w)};
            uint32_t bh[4] = {f2tf(vb.x), f2tf(vb.y), f2tf(vb.z), f2tf(vb.w)};
#pragma unroll
            for (int q = 0; q < 4; ++q) { As[0][row][lc + q] = ah[q]; Bs[0][row][lc + q] = bh[q]; }
            if (NS == 2) {
                As[1][row][lc + 0] = f2tf(va.x - __uint_as_float(ah[0]));
                As[1][row][lc + 1] = f2tf(va.y - __uint_as_float(ah[1]));
                As[1][row][lc + 2] = f2tf(va.z - __uint_as_float(ah[2]));
                As[1][row][lc + 3] = f2tf(va.w - __uint_as_float(ah[3]));
                Bs[1][row][lc + 0] = f2tf(vb.x - __uint_as_float(bh[0]));
                Bs[1][row][lc + 1] = f2tf(vb.y - __uint_as_float(bh[1]));
                Bs[1][row][lc + 2] = f2tf(vb.z - __uint_as_float(bh[2]));
                Bs[1][row][lc + 3] = f2tf(vb.w - __uint_as_float(bh[3]));
            }
        }
        __syncthreads();
#pragma unroll
        for (int kk = 0; kk < 32; kk += 8) {
            uint32_t a[2][4], al[2][4];
            uint32_t b[8][2], bl[8][2];
#pragma unroll
            for (int mf = 0; mf < 2; ++mf) {
                int r = wm * 32 + mf * 16 + grp;
                a[mf][0] = As[0][r][kk + tig];
                a[mf][1] = As[0][r + 8][kk + tig];
                a[mf][2] = As[0][r][kk + tig + 4];
                a[mf][3] = As[0][r + 8][kk + tig + 4];
                if (NS == 2) {
                    al[mf][0] = As[1][r][kk + tig];
                    al[mf][1] = As[1][r + 8][kk + tig];
                    al[mf][2] = As[1][r][kk + tig + 4];
                    al[mf][3] = As[1][r + 8][kk + tig + 4];
                }
            }
#pragma unroll
            for (int nf = 0; nf < 8; ++nf) {
                int col = wn * 64 + nf * 8 + grp;
                b[nf][0] = Bs[0][col][kk + tig];
                b[nf][1] = Bs[0][col][kk + tig + 4];
                if (NS == 2) {
                    bl[nf][0] = Bs[1][col][kk + tig];
                    bl[nf][1] = Bs[1][col][kk + tig + 4];
                }
            }
#pragma unroll
            for (int mf = 0; mf < 2; ++mf)
#pragma unroll
                for (int nf = 0; nf < 8; ++nf) {
                    if (NS == 2) {
                        mma8(c[mf][nf], al[mf], b[nf]);
                        mma8(c[mf][nf], a[mf], bl[nf]);
                    }
                    mma8(c[mf][nf], a[mf], b[nf]);
                }
        }
        __syncthreads();
    }

#pragma unroll
    for (int mf = 0; mf < 2; ++mf) {
        int r0 = m_cta + wm * 32 + mf * 16 + grp;
#pragma unroll
        for (int nf = 0; nf < 8; ++nf) {
            int cn = n_cta + wn * 64 + nf * 8 + tig * 2;
            float v0 = c[mf][nf][0], v1 = c[mf][nf][1];
            float v2 = c[mf][nf][2], v3 = c[mf][nf][3];
            if (bias) {
                float b0 = bias[cn], b1 = bias[cn + 1];
                v0 += b0; v1 += b1; v2 += b0; v3 += b1;
            }
            *(float2*)(C + (size_t)r0 * N + cn)       = make_float2(v0, v1);
            *(float2*)(C + (size_t)(r0 + 8) * N + cn) = make_float2(v2, v3);
        }
    }
}

// ---------------- small kernels ----------------
__global__ void init_node(const int* __restrict__ unit_type, const float* __restrict__ emb) {
    int idx = blockIdx.x * blockDim.x + threadIdx.x;
    if (idx >= NN * NH) return;
    int n = idx >> 7, i = idx & 127;
    g_node[idx] = emb[unit_type[n] * NH + i];
}

__global__ void init_s2s0() {
    int idx = blockIdx.x * blockDim.x + threadIdx.x;
    if (idx < NB * 2 * NH) g_qstar[idx] = 0.0f;
    if (idx < NB * NH) { g_h[idx] = 0.0f; g_c[idx] = 0.0f; }
}

__global__ void permute_w2(const float* __restrict__ w2, const float* __restrict__ b2) {
    int tid = blockIdx.x * blockDim.x + threadIdx.x;
    if (tid >= HH * NH) return;
    int m = tid >> 7, k = tid & 127;
    int i = m & 127, j = m >> 7;
    g_w2p[tid] = w2[(size_t)k * HH + i * NH + j];
    if (k == 0) g_b2p[m] = b2[i * NH + j];
}

__global__ void edge_mlp(const float* __restrict__ ef, const float* __restrict__ w1,
                         const float* __restrict__ b1) {
    int e = blockIdx.x;
    int t = threadIdx.x;  // 128
    __shared__ float efs[NED];
    if (t < NED) efs[t] = ef[e * NED + t];
    __syncthreads();
    float acc = b1[t];
#pragma unroll
    for (int d = 0; d < NED; ++d) acc = fmaf(efs[d], w1[d * NH + t], acc);
    g_hmid[e * NH + t] = fmaxf(acc, 0.0f);
}

__global__ void zero_update() {
    int idx = blockIdx.x * blockDim.x + threadIdx.x;
    if (idx < NN * NH) g_update[idx] = 0.0f;
}

__global__ void relu_update() {
    int idx = blockIdx.x * blockDim.x + threadIdx.x;
    if (idx < NN * NH) g_update[idx] = fmaxf(g_update[idx], 0.0f);
}

// per-edge matvec msg[i] = sum_j T'[e][j][i] * x[node_in[e]][j]; scatter-add
__global__ void msg_scatter(const int* __restrict__ node_in, const int* __restrict__ node_out) {
    int e = blockIdx.x;
    int t = threadIdx.x;  // 128
    __shared__ float xs[NH];
    __shared__ float red[4][NH];
    xs[t] = g_node[node_in[e] * NH + t];
    __syncthreads();
    const int q = t >> 5;          // j-quarter
    const int i0 = (t & 31) * 4;   // 4 output columns
    const float* Te = g_T + (size_t)e * HH;
    float a0 = 0.f, a1 = 0.f, a2 = 0.f, a3 = 0.f;
#pragma unroll 8
    for (int j = q * 32; j < q * 32 + 32; ++j) {
        float4 v = *(const float4*)(Te + (size_t)j * NH + i0);
        float xj = xs[j];
        a0 = fmaf(v.x, xj, a0);
        a1 = fmaf(v.y, xj, a1);
        a2 = fmaf(v.z, xj, a2);
        a3 = fmaf(v.w, xj, a3);
    }
    red[q][i0] = a0; red[q][i0 + 1] = a1; red[q][i0 + 2] = a2; red[q][i0 + 3] = a3;
    __syncthreads();
    float s = red[0][t] + red[1][t] + red[2][t] + red[3][t];
    atomicAdd(&g_update[node_out[e] * NH + t], s);
}

__global__ void gru_gates(const float* __restrict__ bih, const float* __restrict__ bhh) {
    int idx = blockIdx.x * blockDim.x + threadIdx.x;
    if (idx >= NN * NH) return;
    int n = idx >> 7, i = idx & 127;
    const float* gi = g_gi + (size_t)n * 3 * NH;
    const float* gh = g_gh + (size_t)n * 3 * NH;
    float r  = sigm(gi[i] + bih[i] + gh[i] + bhh[i]);
    float z  = sigm(gi[NH + i] + bih[NH + i] + gh[NH + i] + bhh[NH + i]);
    float nn = tanhf(gi[2 * NH + i] + bih[2 * NH + i] + r * (gh[2 * NH + i] + bhh[2 * NH + i]));
    float h  = g_node[idx];
    g_node[idx] = (1.0f - z) * nn + z * h;
}

__global__ void lstm_gates(const float* __restrict__ bih, const float* __restrict__ bhh) {
    int idx = blockIdx.x * blockDim.x + threadIdx.x;
    if (idx >= NB * NH) return;
    int b = idx >> 7, i = idx & 127;
    const float* g1 = g_gl1 + (size_t)b * 4 * NH;
    const float* g2 = g_gl2 + (size_t)b * 4 * NH;
    float gi = g1[i]          + g2[i]          + bih[i]          + bhh[i];
    float gf = g1[NH + i]     + g2[NH + i]     + bih[NH + i]     + bhh[NH + i];
    float gg = g1[2 * NH + i] + g2[2 * NH + i] + bih[2 * NH + i] + bhh[2 * NH + i];
    float go = g1[3 * NH + i] + g2[3 * NH + i] + bih[3 * NH + i] + bhh[3 * NH + i];
    float cc = sigm(gf) * g_c[idx] + sigm(gi) * tanhf(gg);
    float hh = sigm(go) * tanhf(cc);
    g_c[idx] = cc;
    g_h[idx] = hh;
    g_qstar[b * 2 * NH + i] = hh;
}

__global__ void s2s_prod(const int* __restrict__ n2g) {
    int n = blockIdx.x * (blockDim.x >> 5) + (threadIdx.x >> 5);
    int lane = threadIdx.x & 31;
    if (n >= NN) return;
    int g = n2g[n];
    float4 hv = *(const float4*)(g_h + g * NH + lane * 4);
    float4 fv = *(const float4*)(g_node + n * NH + lane * 4);
    float s = hv.x * fv.x + hv.y * fv.y + hv.z * fv.z + hv.w * fv.w;
#pragma unroll
    for (int o = 16; o; o >>= 1) s += __shfl_xor_sync(0xffffffffu, s, o);
    if (lane == 0) g_prod[n] = s;
}

__global__ void s2s_init() {
    int idx = blockIdx.x * blockDim.x + threadIdx.x;
    if (idx < NB * NH) {
        int b = idx >> 7, i = idx & 127;
        g_qstar[b * 2 * NH + NH + i] = 0.0f;
    }
    if (idx < NB) { g_m[idx] = 0u; g_d[idx] = 0.0f; }
}

__global__ void s2s_max(const int* __restrict__ n2g) {
    int n = blockIdx.x * blockDim.x + threadIdx.x;
    if (n >= NN) return;
    atomicMax(&g_m[n2g[n]], fkey(g_prod[n]));
}

__global__ void s2s_expsum(const int* __restrict__ n2g) {
    int n = blockIdx.x * blockDim.x + threadIdx.x;
    if (n >= NN) return;
    int g = n2g[n];
    float e = expf(g_prod[n] - fdekey(g_m[g]));
    g_prod[n] = e;
    atomicAdd(&g_d[g], e);
}

__global__ void s2s_pool(const int* __restrict__ n2g) {
    int n = blockIdx.x;
    int t = threadIdx.x;  // 128
    int g = n2g[n];
    float attn = g_prod[n] / g_d[g];
    atomicAdd(&g_qstar[g * 2 * NH + NH + t], attn * g_node[n * NH + t]);
}

__global__ void copy_out(float* __restrict__ out, int out_size) {
    int idx = blockIdx.x * blockDim.x + threadIdx.x;
    if (idx >= out_size) return;
    if (idx < NB * 2 * NH) out[idx] = g_qstar[idx];
    else if (idx < NB * 2 * NH + NN * NH) out[idx] = g_node[idx - NB * 2 * NH];
}

// ---------------- launch ----------------
extern "C" void kernel_launch(void* const* d_in, const int* in_sizes, int n_in,
                              void* d_out, int out_size) {
    const int*   unit_type    = (const int*)d_in[0];
    const int*   node_in      = (const int*)d_in[1];
    const int*   node_out     = (const int*)d_in[2];
    const int*   node2graph   = (const int*)d_in[3];
    const float* edge_feature = (const float*)d_in[4];
    const float* embedding    = (const float*)d_in[5];
    const float* mlp_w1       = (const float*)d_in[6];
    const float* mlp_b1       = (const float*)d_in[7];
    const float* mlp_w2       = (const float*)d_in[8];
    const float* mlp_b2       = (const float*)d_in[9];
    const float* gru_w_ih     = (const float*)d_in[10];
    const float* gru_w_hh     = (const float*)d_in[11];
    const float* gru_b_ih     = (const float*)d_in[12];
    const float* gru_b_hh     = (const float*)d_in[13];
    const float* lstm_w_ih    = (const float*)d_in[14];
    const float* lstm_w_hh    = (const float*)d_in[15];
    const float* lstm_b_ih    = (const float*)d_in[16];
    const float* lstm_b_hh    = (const float*)d_in[17];
    float* out = (float*)d_out;

    float *p_hmid, *p_w2p, *p_b2p, *p_T, *p_update, *p_node, *p_gi, *p_gh,
          *p_qstar, *p_h, *p_gl1, *p_gl2;
    cudaGetSymbolAddress((void**)&p_hmid,   g_hmid);
    cudaGetSymbolAddress((void**)&p_w2p,    g_w2p);
    cudaGetSymbolAddress((void**)&p_b2p,    g_b2p);
    cudaGetSymbolAddress((void**)&p_T,      g_T);
    cudaGetSymbolAddress((void**)&p_update, g_update);
    cudaGetSymbolAddress((void**)&p_node,   g_node);
    cudaGetSymbolAddress((void**)&p_gi,     g_gi);
    cudaGetSymbolAddress((void**)&p_gh,     g_gh);
    cudaGetSymbolAddress((void**)&p_qstar,  g_qstar);
    cudaGetSymbolAddress((void**)&p_h,      g_h);
    cudaGetSymbolAddress((void**)&p_gl1,    g_gl1);
    cudaGetSymbolAddress((void**)&p_gl2,    g_gl2);

    const int SM1 = 2 * 128 * 36 * 4;   // 36 KB  (NS=1)
    const int SM2 = 4 * 128 * 36 * 4;   // 73 KB  (NS=2)
    cudaFuncSetAttribute(gemm_tf32<2>, cudaFuncAttributeMaxDynamicSharedMemorySize, SM2);

    init_node<<<(NN * NH + 255) / 256, 256>>>(unit_type, embedding);
    init_s2s0<<<(NB * 2 * NH + 255) / 256, 256>>>();
    permute_w2<<<(HH * NH + 255) / 256, 256>>>(mlp_w2, mlp_b2);
    edge_mlp<<<NE, 128>>>(edge_feature, mlp_w1, mlp_b1);

    // transform = hmid @ w2p^T  (fp32 out, layout [e][j][i])
    gemm_tf32<1><<<dim3(HH / 128, NE / 128), 256, SM1>>>(p_hmid, p_w2p, p_T, p_b2p,
                                                         NE, HH, NH);

    for (int l = 0; l < 3; ++l) {
        zero_update<<<(NN * NH + 255) / 256, 256>>>();
        msg_scatter<<<NE, 128>>>(node_in, node_out);
        relu_update<<<(NN * NH + 255) / 256, 256>>>();
        gemm_tf32<2><<<dim3(3, NN / 128), 256, SM2>>>(p_update, gru_w_ih, p_gi, nullptr,
                                                      NN, 3 * NH, NH);
        gemm_tf32<2><<<dim3(3, NN / 128), 256, SM2>>>(p_node, gru_w_hh, p_gh, nullptr,
                                                      NN, 3 * NH, NH);
        gru_gates<<<(NN * NH + 255) / 256, 256>>>(gru_b_ih, gru_b_hh);
    }

    for (int s = 0; s < 3; ++s) {
        gemm_tf32<2><<<dim3(4, 4), 256, SM2>>>(p_qstar, lstm_w_ih, p_gl1, nullptr,
                                               NB, 4 * NH, 2 * NH);
        gemm_tf32<2><<<dim3(4, 4), 256, SM2>>>(p_h, lstm_w_hh, p_gl2, nullptr,
                                               NB, 4 * NH, NH);
        lstm_gates<<<(NB * NH + 255) / 256, 256>>>(lstm_b_ih, lstm_b_hh);
        s2s_prod<<<(NN + 7) / 8, 256>>>(node2graph);
        s2s_init<<<(NB * NH + 255) / 256, 256>>>();
        s2s_max<<<(NN + 255) / 256, 256>>>(node2graph);
        s2s_expsum<<<(NN + 255) / 256, 256>>>(node2graph);
        s2s_pool<<<NN, 128>>>(node2graph);
    }

    copy_out<<<(out_size + 255) / 256, 256>>>(out, out_size);
}

// round 4
// speedup vs baseline: 1.2322x; 1.2322x over previous
#include <cuda_runtime.h>
#include <cuda_bf16.h>
#include <cstdint>
#include <cstdio>

// ---------------- problem constants ----------------
#define NH   128        // hidden
#define NB   512        // graphs
#define NN   8192       // nodes
#define NE   16384      // edges
#define NED  32         // edge dim
#define HH   16384      // H*H

// ---------------- device scratch ----------------
__device__ float g_hmid[NE * NH];                       // tf32-rounded
__device__ float g_w2p[HH * NH];                        // tf32-rounded, [m=j*128+i][k]
__device__ float g_b2p[HH];
__device__ float g_T[(size_t)NE * HH];                  // 1 GiB, [e][j][i] fp32
__device__ float g_node[NN * NH];
__device__ float g_update[NN * NH];
__device__ float g_gi[NN * 3 * NH];
__device__ float g_gh[NN * 3 * NH];
__device__ float g_h[NB * NH];
__device__ float g_c[NB * NH];
__device__ float g_qstar[NB * 2 * NH];
__device__ float g_gl1[NB * 4 * NH];
__device__ float g_gl2[NB * 4 * NH];
__device__ float g_prod[NN];
__device__ unsigned int g_m[NB];
__device__ float g_d[NB];
// split (hi|lo) operand buffers for near-fp32 tf32 GEMMs
__device__ float g_upd2[NN * 2 * NH];
__device__ float g_node2[NN * 2 * NH];
__device__ float g_wih2[3 * NH * 2 * NH];
__device__ float g_whh2[3 * NH * 2 * NH];
__device__ float g_lwih2[4 * NH * 4 * NH];
__device__ float g_lwhh2[4 * NH * 2 * NH];
__device__ float g_q2[NB * 4 * NH];
__device__ float g_h2[NB * 2 * NH];

// ---------------- helpers ----------------
__device__ __forceinline__ uint32_t f2tf(float f) {
    uint32_t u;
    asm("cvt.rna.tf32.f32 %0, %1;" : "=r"(u) : "f"(f));
    return u;
}
__device__ __forceinline__ float tf32r(float f) { return __uint_as_float(f2tf(f)); }

__device__ __forceinline__ void mma8(float* c, const uint32_t* a, const uint32_t* b) {
    asm volatile(
        "mma.sync.aligned.m16n8k8.row.col.f32.tf32.tf32.f32 "
        "{%0,%1,%2,%3},{%4,%5,%6,%7},{%8,%9},{%0,%1,%2,%3};"
        : "+f"(c[0]), "+f"(c[1]), "+f"(c[2]), "+f"(c[3])
        : "r"(a[0]), "r"(a[1]), "r"(a[2]), "r"(a[3]), "r"(b[0]), "r"(b[1]));
}

__device__ __forceinline__ float sigm(float x) { return 1.0f / (1.0f + expf(-x)); }

__device__ __forceinline__ unsigned int fkey(float f) {
    unsigned int b = __float_as_uint(f);
    return (b & 0x80000000u) ? ~b : (b | 0x80000000u);
}
__device__ __forceinline__ float fdekey(unsigned int k) {
    unsigned int b = (k & 0x80000000u) ? (k & 0x7fffffffu) : ~k;
    return __uint_as_float(b);
}

// ---------------- tf32 GEMM, cp.async double-buffered ----------------
// C[M,N] = A[M,K] @ B[N,K]^T (+bias[n]). Operands pre-rounded to tf32 bits.
// M,N multiples of 128; K multiple of 16. 256 threads; warp tile 32x64.
__global__ void __launch_bounds__(256, 2)
gemm_db(const float* __restrict__ A, const float* __restrict__ B,
        float* __restrict__ C, const float* __restrict__ bias,
        int M, int N, int K) {
    __shared__ float As[2][128][20];
    __shared__ float Bs[2][128][20];

    const int tid  = threadIdx.x;
    const int warp = tid >> 5, lane = tid & 31;
    const int grp  = lane >> 2, tig = lane & 3;
    const int wm   = warp & 3, wn = warp >> 2;
    const int m0 = blockIdx.y * 128;
    const int n0 = blockIdx.x * 128;

    float c[2][8][4] = {};

    const int ldrow = tid >> 1;                 // rows 0..127 (2 thr/row)
    const int ldc4  = (tid & 1) * 8;            // 0 or 8 (two float4 each)

    auto load_chunk = [&](int buf, int k0) {
#pragma unroll
        for (int p = 0; p < 2; ++p) {
            int c4 = ldc4 + p * 4;
            uint32_t sa = (uint32_t)__cvta_generic_to_shared(&As[buf][ldrow][c4]);
            uint32_t sb = (uint32_t)__cvta_generic_to_shared(&Bs[buf][ldrow][c4]);
            const float* ga = A + (size_t)(m0 + ldrow) * K + k0 + c4;
            const float* gb = B + (size_t)(n0 + ldrow) * K + k0 + c4;
            asm volatile("cp.async.cg.shared.global [%0], [%1], 16;" :: "r"(sa), "l"(ga));
            asm volatile("cp.async.cg.shared.global [%0], [%1], 16;" :: "r"(sb), "l"(gb));
        }
        asm volatile("cp.async.commit_group;");
    };

    const int nch = K >> 4;
    load_chunk(0, 0);

    for (int ch = 0; ch < nch; ++ch) {
        if (ch + 1 < nch) {
            load_chunk((ch + 1) & 1, (ch + 1) << 4);
            asm volatile("cp.async.wait_group 1;");
        } else {
            asm volatile("cp.async.wait_group 0;");
        }
        __syncthreads();
        const int buf = ch & 1;
#pragma unroll
        for (int kk = 0; kk < 16; kk += 8) {
            uint32_t a[2][4];
            uint32_t b[8][2];
#pragma unroll
            for (int mf = 0; mf < 2; ++mf) {
                int r = wm * 32 + mf * 16 + grp;
                a[mf][0] = __float_as_uint(As[buf][r][kk + tig]);
                a[mf][1] = __float_as_uint(As[buf][r + 8][kk + tig]);
                a[mf][2] = __float_as_uint(As[buf][r][kk + tig + 4]);
                a[mf][3] = __float_as_uint(As[buf][r + 8][kk + tig + 4]);
            }
#pragma unroll
            for (int nf = 0; nf < 8; ++nf) {
                int col = wn * 64 + nf * 8 + grp;
                b[nf][0] = __float_as_uint(Bs[buf][col][kk + tig]);
                b[nf][1] = __float_as_uint(Bs[buf][col][kk + tig + 4]);
            }
#pragma unroll
            for (int mf = 0; mf < 2; ++mf)
#pragma unroll
                for (int nf = 0; nf < 8; ++nf)
                    mma8(c[mf][nf], a[mf], b[nf]);
        }
        __syncthreads();
    }

#pragma unroll
    for (int mf = 0; mf < 2; ++mf) {
        int r0 = m0 + wm * 32 + mf * 16 + grp;
#pragma unroll
        for (int nf = 0; nf < 8; ++nf) {
            int cn = n0 + wn * 64 + nf * 8 + tig * 2;
            float v0 = c[mf][nf][0], v1 = c[mf][nf][1];
            float v2 = c[mf][nf][2], v3 = c[mf][nf][3];
            if (bias) {
                float b0 = bias[cn], b1 = bias[cn + 1];
                v0 += b0; v1 += b1; v2 += b0; v3 += b1;
            }
            *(float2*)(C + (size_t)r0 * N + cn)       = make_float2(v0, v1);
            *(float2*)(C + (size_t)(r0 + 8) * N + cn) = make_float2(v2, v3);
        }
    }
}

// ---------------- prep kernels ----------------
// split x -> [tf32_hi | tf32_lo] along K (optionally relu first)
__global__ void split2(const float* __restrict__ in, float* __restrict__ out,
                       int R, int K, int relu) {
    int idx = blockIdx.x * blockDim.x + threadIdx.x;
    if (idx >= R * K) return;
    int r = idx / K, ccol = idx - r * K;
    float x = in[idx];
    if (relu) x = fmaxf(x, 0.0f);
    float hi = tf32r(x);
    float lo = tf32r(x - hi);
    out[(size_t)r * 2 * K + ccol]     = hi;
    out[(size_t)r * 2 * K + K + ccol] = lo;
}

// w2 [k][i*128+j] -> g_w2p [(j*128+i)][k], tf32-rounded, coalesced tiles
__global__ void w2_transpose(const float* __restrict__ w2) {
    __shared__ float s[32][33];
    int k0 = blockIdx.x * 32, j0 = blockIdx.y * 32, i = blockIdx.z;
    int tx = threadIdx.x, ty = threadIdx.y;
#pragma unroll
    for (int r = 0; r < 4; ++r) {
        int kk = ty + r * 8;
        s[kk][tx] = w2[(size_t)(k0 + kk) * HH + i * NH + j0 + tx];
    }
    __syncthreads();
#pragma unroll
    for (int r = 0; r < 4; ++r) {
        int jj = ty + r * 8;
        int m = (j0 + jj) * NH + i;
        g_w2p[(size_t)m * NH + k0 + tx] = tf32r(s[tx][jj]);
    }
}

__global__ void bias_perm(const float* __restrict__ b2) {
    int m = blockIdx.x * blockDim.x + threadIdx.x;
    if (m < HH) g_b2p[m] = b2[(m & 127) * NH + (m >> 7)];
}

__global__ void edge_mlp(const float* __restrict__ ef, const float* __restrict__ w1,
                         const float* __restrict__ b1) {
    int e = blockIdx.x;
    int t = threadIdx.x;  // 128
    __shared__ float efs[NED];
    if (t < NED) efs[t] = ef[e * NED + t];
    __syncthreads();
    float acc = b1[t];
#pragma unroll
    for (int d = 0; d < NED; ++d) acc = fmaf(efs[d], w1[d * NH + t], acc);
    g_hmid[e * NH + t] = tf32r(fmaxf(acc, 0.0f));
}

// ---------------- elementwise / graph kernels ----------------
__global__ void init_node(const int* __restrict__ unit_type, const float* __restrict__ emb) {
    int idx = blockIdx.x * blockDim.x + threadIdx.x;
    if (idx >= NN * NH) return;
    int n = idx >> 7, i = idx & 127;
    g_node[idx] = emb[unit_type[n] * NH + i];
}

__global__ void init_s2s0() {
    int idx = blockIdx.x * blockDim.x + threadIdx.x;
    if (idx < NB * 2 * NH) g_qstar[idx] = 0.0f;
    if (idx < NB * NH) { g_h[idx] = 0.0f; g_c[idx] = 0.0f; }
}

__global__ void zero_update() {
    int idx = blockIdx.x * blockDim.x + threadIdx.x;
    if (idx < NN * NH) g_update[idx] = 0.0f;
}

// per-edge matvec msg[i] = sum_j T'[e][j][i] * x[node_in[e]][j]; scatter-add
__global__ void msg_scatter(const int* __restrict__ node_in, const int* __restrict__ node_out) {
    int e = blockIdx.x;
    int t = threadIdx.x;  // 128
    __shared__ float xs[NH];
    __shared__ float red[4][NH];
    xs[t] = g_node[node_in[e] * NH + t];
    __syncthreads();
    const int q = t >> 5;
    const int i0 = (t & 31) * 4;
    const float* Te = g_T + (size_t)e * HH;
    float a0 = 0.f, a1 = 0.f, a2 = 0.f, a3 = 0.f;
#pragma unroll 8
    for (int j = q * 32; j < q * 32 + 32; ++j) {
        float4 v = *(const float4*)(Te + (size_t)j * NH + i0);
        float xj = xs[j];
        a0 = fmaf(v.x, xj, a0);
        a1 = fmaf(v.y, xj, a1);
        a2 = fmaf(v.z, xj, a2);
        a3 = fmaf(v.w, xj, a3);
    }
    red[q][i0] = a0; red[q][i0 + 1] = a1; red[q][i0 + 2] = a2; red[q][i0 + 3] = a3;
    __syncthreads();
    float s = red[0][t] + red[1][t] + red[2][t] + red[3][t];
    atomicAdd(&g_update[node_out[e] * NH + t], s);
}

__global__ void gru_gates(const float* __restrict__ bih, const float* __restrict__ bhh) {
    int idx = blockIdx.x * blockDim.x + threadIdx.x;
    if (idx >= NN * NH) return;
    int n = idx >> 7, i = idx & 127;
    const float* gi = g_gi + (size_t)n * 3 * NH;
    const float* gh = g_gh + (size_t)n * 3 * NH;
    float r  = sigm(gi[i] + bih[i] + gh[i] + bhh[i]);
    float z  = sigm(gi[NH + i] + bih[NH + i] + gh[NH + i] + bhh[NH + i]);
    float nn = tanhf(gi[2 * NH + i] + bih[2 * NH + i] + r * (gh[2 * NH + i] + bhh[2 * NH + i]));
    float h  = g_node[idx];
    g_node[idx] = (1.0f - z) * nn + z * h;
}

__global__ void lstm_gates(const float* __restrict__ bih, const float* __restrict__ bhh) {
    int idx = blockIdx.x * blockDim.x + threadIdx.x;
    if (idx >= NB * NH) return;
    int b = idx >> 7, i = idx & 127;
    const float* g1 = g_gl1 + (size_t)b * 4 * NH;
    const float* g2 = g_gl2 + (size_t)b * 4 * NH;
    float gi = g1[i]          + g2[i]          + bih[i]          + bhh[i];
    float gf = g1[NH + i]     + g2[NH + i]     + bih[NH + i]     + bhh[NH + i];
    float gg = g1[2 * NH + i] + g2[2 * NH + i] + bih[2 * NH + i] + bhh[2 * NH + i];
    float go = g1[3 * NH + i] + g2[3 * NH + i] + bih[3 * NH + i] + bhh[3 * NH + i];
    float cc = sigm(gf) * g_c[idx] + sigm(gi) * tanhf(gg);
    float hh = sigm(go) * tanhf(cc);
    g_c[idx] = cc;
    g_h[idx] = hh;
    g_qstar[b * 2 * NH + i] = hh;
}

__global__ void s2s_prod(const int* __restrict__ n2g) {
    int n = blockIdx.x * (blockDim.x >> 5) + (threadIdx.x >> 5);
    int lane = threadIdx.x & 31;
    if (n >= NN) return;
    int g = n2g[n];
    float4 hv = *(const float4*)(g_h + g * NH + lane * 4);
    float4 fv = *(const float4*)(g_node + n * NH + lane * 4);
    float s = hv.x * fv.x + hv.y * fv.y + hv.z * fv.z + hv.w * fv.w;
#pragma unroll
    for (int o = 16; o; o >>= 1) s += __shfl_xor_sync(0xffffffffu, s, o);
    if (lane == 0) g_prod[n] = s;
}

__global__ void s2s_init() {
    int idx = blockIdx.x * blockDim.x + threadIdx.x;
    if (idx < NB * NH) {
        int b = idx >> 7, i = idx & 127;
        g_qstar[b * 2 * NH + NH + i] = 0.0f;
    }
    if (idx < NB) { g_m[idx] = 0u; g_d[idx] = 0.0f; }
}

__global__ void s2s_max(const int* __restrict__ n2g) {
    int n = blockIdx.x * blockDim.x + threadIdx.x;
    if (n >= NN) return;
    atomicMax(&g_m[n2g[n]], fkey(g_prod[n]));
}

__global__ void s2s_expsum(const int* __restrict__ n2g) {
    int n = blockIdx.x * blockDim.x + threadIdx.x;
    if (n >= NN) return;
    int g = n2g[n];
    float e = expf(g_prod[n] - fdekey(g_m[g]));
    g_prod[n] = e;
    atomicAdd(&g_d[g], e);
}

__global__ void s2s_pool(const int* __restrict__ n2g) {
    int n = blockIdx.x;
    int t = threadIdx.x;  // 128
    int g = n2g[n];
    float attn = g_prod[n] / g_d[g];
    atomicAdd(&g_qstar[g * 2 * NH + NH + t], attn * g_node[n * NH + t]);
}

__global__ void copy_out(float* __restrict__ out, int out_size) {
    int idx = blockIdx.x * blockDim.x + threadIdx.x;
    if (idx >= out_size) return;
    if (idx < NB * 2 * NH) out[idx] = g_qstar[idx];
    else if (idx < NB * 2 * NH + NN * NH) out[idx] = g_node[idx - NB * 2 * NH];
}

// ---------------- launch ----------------
extern "C" void kernel_launch(void* const* d_in, const int* in_sizes, int n_in,
                              void* d_out, int out_size) {
    const int*   unit_type    = (const int*)d_in[0];
    const int*   node_in      = (const int*)d_in[1];
    const int*   node_out     = (const int*)d_in[2];
    const int*   node2graph   = (const int*)d_in[3];
    const float* edge_feature = (const float*)d_in[4];
    const float* embedding    = (const float*)d_in[5];
    const float* mlp_w1       = (const float*)d_in[6];
    const float* mlp_b1       = (const float*)d_in[7];
    const float* mlp_w2       = (const float*)d_in[8];
    const float* mlp_b2       = (const float*)d_in[9];
    const float* gru_w_ih     = (const float*)d_in[10];
    const float* gru_w_hh     = (const float*)d_in[11];
    const float* gru_b_ih     = (const float*)d_in[12];
    const float* gru_b_hh     = (const float*)d_in[13];
    const float* lstm_w_ih    = (const float*)d_in[14];
    const float* lstm_w_hh    = (const float*)d_in[15];
    const float* lstm_b_ih    = (const float*)d_in[16];
    const float* lstm_b_hh    = (const float*)d_in[17];
    float* out = (float*)d_out;

    float *p_hmid, *p_w2p, *p_b2p, *p_T, *p_update, *p_node, *p_gi, *p_gh,
          *p_qstar, *p_h, *p_gl1, *p_gl2,
          *p_upd2, *p_node2, *p_wih2, *p_whh2, *p_lwih2, *p_lwhh2, *p_q2, *p_h2;
    cudaGetSymbolAddress((void**)&p_hmid,   g_hmid);
    cudaGetSymbolAddress((void**)&p_w2p,    g_w2p);
    cudaGetSymbolAddress((void**)&p_b2p,    g_b2p);
    cudaGetSymbolAddress((void**)&p_T,      g_T);
    cudaGetSymbolAddress((void**)&p_update, g_update);
    cudaGetSymbolAddress((void**)&p_node,   g_node);
    cudaGetSymbolAddress((void**)&p_gi,     g_gi);
    cudaGetSymbolAddress((void**)&p_gh,     g_gh);
    cudaGetSymbolAddress((void**)&p_qstar,  g_qstar);
    cudaGetSymbolAddress((void**)&p_h,      g_h);
    cudaGetSymbolAddress((void**)&p_gl1,    g_gl1);
    cudaGetSymbolAddress((void**)&p_gl2,    g_gl2);
    cudaGetSymbolAddress((void**)&p_upd2,   g_upd2);
    cudaGetSymbolAddress((void**)&p_node2,  g_node2);
    cudaGetSymbolAddress((void**)&p_wih2,   g_wih2);
    cudaGetSymbolAddress((void**)&p_whh2,   g_whh2);
    cudaGetSymbolAddress((void**)&p_lwih2,  g_lwih2);
    cudaGetSymbolAddress((void**)&p_lwhh2,  g_lwhh2);
    cudaGetSymbolAddress((void**)&p_q2,     g_q2);
    cudaGetSymbolAddress((void**)&p_h2,     g_h2);

    init_node<<<(NN * NH + 255) / 256, 256>>>(unit_type, embedding);
    init_s2s0<<<(NB * 2 * NH + 255) / 256, 256>>>();
    w2_transpose<<<dim3(4, 4, 128), dim3(32, 8)>>>(mlp_w2);
    bias_perm<<<(HH + 255) / 256, 256>>>(mlp_b2);
    edge_mlp<<<NE, 128>>>(edge_feature, mlp_w1, mlp_b1);

    // weight splits (hi|lo along K)
    split2<<<(3 * NH * NH + 255) / 256, 256>>>(gru_w_ih,  p_wih2,  3 * NH, NH, 0);
    split2<<<(3 * NH * NH + 255) / 256, 256>>>(gru_w_hh,  p_whh2,  3 * NH, NH, 0);
    split2<<<(4 * NH * 2 * NH + 255) / 256, 256>>>(lstm_w_ih, p_lwih2, 4 * NH, 2 * NH, 0);
    split2<<<(4 * NH * NH + 255) / 256, 256>>>(lstm_w_hh, p_lwhh2, 4 * NH, NH, 0);

    // transform = hmid @ w2p^T  (fp32 out, layout [e][j][i])
    gemm_db<<<dim3(HH / 128, NE / 128), 256>>>(p_hmid, p_w2p, p_T, p_b2p, NE, HH, NH);

    for (int l = 0; l < 3; ++l) {
        zero_update<<<(NN * NH + 255) / 256, 256>>>();
        msg_scatter<<<NE, 128>>>(node_in, node_out);
        split2<<<(NN * NH + 255) / 256, 256>>>(p_update, p_upd2,  NN, NH, 1);  // relu fused
        split2<<<(NN * NH + 255) / 256, 256>>>(p_node,   p_node2, NN, NH, 0);
        gemm_db<<<dim3(3, NN / 128), 256>>>(p_upd2,  p_wih2, p_gi, nullptr, NN, 3 * NH, 2 * NH);
        gemm_db<<<dim3(3, NN / 128), 256>>>(p_node2, p_whh2, p_gh, nullptr, NN, 3 * NH, 2 * NH);
        gru_gates<<<(NN * NH + 255) / 256, 256>>>(gru_b_ih, gru_b_hh);
    }

    for (int s = 0; s < 3; ++s) {
        split2<<<(NB * 2 * NH + 255) / 256, 256>>>(p_qstar, p_q2, NB, 2 * NH, 0);
        split2<<<(NB * NH + 255) / 256, 256>>>(p_h, p_h2, NB, NH, 0);
        gemm_db<<<dim3(4, 4), 256>>>(p_q2, p_lwih2, p_gl1, nullptr, NB, 4 * NH, 4 * NH);
        gemm_db<<<dim3(4, 4), 256>>>(p_h2, p_lwhh2, p_gl2, nullptr, NB, 4 * NH, 2 * NH);
        lstm_gates<<<(NB * NH + 255) / 256, 256>>>(lstm_b_ih, lstm_b_hh);
        s2s_prod<<<(NN + 7) / 8, 256>>>(node2graph);
        s2s_init<<<(NB * NH + 255) / 256, 256>>>();
        s2s_max<<<(NN + 255) / 256, 256>>>(node2graph);
        s2s_expsum<<<(NN + 255) / 256, 256>>>(node2graph);
        s2s_pool<<<NN, 128>>>(node2graph);
    }

    copy_out<<<(out_size + 255) / 256, 256>>>(out, out_size);
}

// round 6
// speedup vs baseline: 1.4420x; 1.1702x over previous
#include <cuda_runtime.h>
#include <cuda_bf16.h>
#include <cuda_fp16.h>
#include <cstdint>
#include <cstdio>

// ---------------- problem constants ----------------
#define NH   128        // hidden
#define NB   512        // graphs
#define NN   8192       // nodes
#define NE   16384      // edges
#define NED  32         // edge dim
#define HH   16384      // H*H

// ---------------- device scratch ----------------
__device__ float g_hmid[NE * NH];                       // tf32-rounded
__device__ float g_w2p[HH * NH];                        // tf32-rounded, [m=j*128+i][k]
__device__ float g_b2p[HH];
__device__ __half g_T[(size_t)NE * HH];                 // 512 MB, [e][j][i] fp16
__device__ float g_node[NN * NH];
__device__ float g_update[NN * NH];
__device__ float g_gi[NN * 3 * NH];
__device__ float g_gh[NN * 3 * NH];
__device__ float g_h[NB * NH];
__device__ float g_c[NB * NH];
__device__ float g_qstar[NB * 2 * NH];
__device__ float g_gl1[NB * 4 * NH];
__device__ float g_gl2[NB * 4 * NH];
__device__ float g_prod[NN];
__device__ unsigned int g_m[NB];
__device__ float g_d[NB];
// split (hi|lo) operand buffers for near-fp32 tf32 GEMMs
__device__ float g_upd2[NN * 2 * NH];
__device__ float g_node2[NN * 2 * NH];
__device__ float g_wih2[3 * NH * 2 * NH];
__device__ float g_whh2[3 * NH * 2 * NH];
__device__ float g_lwih2[4 * NH * 4 * NH];
__device__ float g_lwhh2[4 * NH * 2 * NH];
__device__ float g_q2[NB * 4 * NH];
__device__ float g_h2[NB * 2 * NH];

// ---------------- helpers ----------------
__device__ __forceinline__ uint32_t f2tf(float f) {
    uint32_t u;
    asm("cvt.rna.tf32.f32 %0, %1;" : "=r"(u) : "f"(f));
    return u;
}
__device__ __forceinline__ float tf32r(float f) { return __uint_as_float(f2tf(f)); }

__device__ __forceinline__ void mma8(float* c, const uint32_t* a, const uint32_t* b) {
    asm volatile(
        "mma.sync.aligned.m16n8k8.row.col.f32.tf32.tf32.f32 "
        "{%0,%1,%2,%3},{%4,%5,%6,%7},{%8,%9},{%0,%1,%2,%3};"
        : "+f"(c[0]), "+f"(c[1]), "+f"(c[2]), "+f"(c[3])
        : "r"(a[0]), "r"(a[1]), "r"(a[2]), "r"(a[3]), "r"(b[0]), "r"(b[1]));
}

__device__ __forceinline__ float sigm(float x) { return 1.0f / (1.0f + expf(-x)); }

__device__ __forceinline__ unsigned int fkey(float f) {
    unsigned int b = __float_as_uint(f);
    return (b & 0x80000000u) ? ~b : (b | 0x80000000u);
}
__device__ __forceinline__ float fdekey(unsigned int k) {
    unsigned int b = (k & 0x80000000u) ? (k & 0x7fffffffu) : ~k;
    return __uint_as_float(b);
}

// ---------------- tf32 GEMM, cp.async double-buffered ----------------
// C[M,N] = A[M,K] @ B[N,K]^T (+bias[n]). Operands pre-rounded to tf32 bits.
// Writes fp32 (C) or fp16 (Ch). M,N mult of 128; K mult of 16. 256 thr.
__global__ void __launch_bounds__(256, 2)
gemm_db(const float* __restrict__ A, const float* __restrict__ B,
        float* __restrict__ C, __half* __restrict__ Ch,
        const float* __restrict__ bias, int M, int N, int K) {
    __shared__ float As[2][128][20];
    __shared__ float Bs[2][128][20];

    const int tid  = threadIdx.x;
    const int warp = tid >> 5, lane = tid & 31;
    const int grp  = lane >> 2, tig = lane & 3;
    const int wm   = warp & 3, wn = warp >> 2;
    const int m0 = blockIdx.y * 128;
    const int n0 = blockIdx.x * 128;

    float c[2][8][4] = {};

    const int ldrow = tid >> 1;                 // rows 0..127 (2 thr/row)
    const int ldc4  = (tid & 1) * 8;            // 0 or 8

    auto load_chunk = [&](int buf, int k0) {
#pragma unroll
        for (int p = 0; p < 2; ++p) {
            int c4 = ldc4 + p * 4;
            uint32_t sa = (uint32_t)__cvta_generic_to_shared(&As[buf][ldrow][c4]);
            uint32_t sb = (uint32_t)__cvta_generic_to_shared(&Bs[buf][ldrow][c4]);
            const float* ga = A + (size_t)(m0 + ldrow) * K + k0 + c4;
            const float* gb = B + (size_t)(n0 + ldrow) * K + k0 + c4;
            asm volatile("cp.async.cg.shared.global [%0], [%1], 16;" :: "r"(sa), "l"(ga));
            asm volatile("cp.async.cg.shared.global [%0], [%1], 16;" :: "r"(sb), "l"(gb));
        }
        asm volatile("cp.async.commit_group;");
    };

    const int nch = K >> 4;
    load_chunk(0, 0);

    for (int ch = 0; ch < nch; ++ch) {
        if (ch + 1 < nch) {
            load_chunk((ch + 1) & 1, (ch + 1) << 4);
            asm volatile("cp.async.wait_group 1;");
        } else {
            asm volatile("cp.async.wait_group 0;");
        }
        __syncthreads();
        const int buf = ch & 1;
#pragma unroll
        for (int kk = 0; kk < 16; kk += 8) {
            uint32_t a[2][4];
            uint32_t b[8][2];
#pragma unroll
            for (int mf = 0; mf < 2; ++mf) {
                int r = wm * 32 + mf * 16 + grp;
                a[mf][0] = __float_as_uint(As[buf][r][kk + tig]);
                a[mf][1] = __float_as_uint(As[buf][r + 8][kk + tig]);
                a[mf][2] = __float_as_uint(As[buf][r][kk + tig + 4]);
                a[mf][3] = __float_as_uint(As[buf][r + 8][kk + tig + 4]);
            }
#pragma unroll
            for (int nf = 0; nf < 8; ++nf) {
                int col = wn * 64 + nf * 8 + grp;
                b[nf][0] = __float_as_uint(Bs[buf][col][kk + tig]);
                b[nf][1] = __float_as_uint(Bs[buf][col][kk + tig + 4]);
            }
#pragma unroll
            for (int mf = 0; mf < 2; ++mf)
#pragma unroll
                for (int nf = 0; nf < 8; ++nf)
                    mma8(c[mf][nf], a[mf], b[nf]);
        }
        __syncthreads();
    }

#pragma unroll
    for (int mf = 0; mf < 2; ++mf) {
        int r0 = m0 + wm * 32 + mf * 16 + grp;
#pragma unroll
        for (int nf = 0; nf < 8; ++nf) {
            int cn = n0 + wn * 64 + nf * 8 + tig * 2;
            float v0 = c[mf][nf][0], v1 = c[mf][nf][1];
            float v2 = c[mf][nf][2], v3 = c[mf][nf][3];
            if (bias) {
                float b0 = bias[cn], b1 = bias[cn + 1];
                v0 += b0; v1 += b1; v2 += b0; v3 += b1;
            }
            if (Ch) {
                *(__half2*)(Ch + (size_t)r0 * N + cn)       = __floats2half2_rn(v0, v1);
                *(__half2*)(Ch + (size_t)(r0 + 8) * N + cn) = __floats2half2_rn(v2, v3);
            } else {
                *(float2*)(C + (size_t)r0 * N + cn)       = make_float2(v0, v1);
                *(float2*)(C + (size_t)(r0 + 8) * N + cn) = make_float2(v2, v3);
            }
        }
    }
}

// ---------------- prep kernels ----------------
__global__ void split2(const float* __restrict__ in, float* __restrict__ out,
                       int R, int K, int relu) {
    int idx = blockIdx.x * blockDim.x + threadIdx.x;
    if (idx >= R * K) return;
    int r = idx / K, ccol = idx - r * K;
    float x = in[idx];
    if (relu) x = fmaxf(x, 0.0f);
    float hi = tf32r(x);
    float lo = tf32r(x - hi);
    out[(size_t)r * 2 * K + ccol]     = hi;
    out[(size_t)r * 2 * K + K + ccol] = lo;
}

// w2 [k][i*128+j] -> g_w2p [(j*128+i)][k], tf32-rounded, coalesced tiles
__global__ void w2_transpose(const float* __restrict__ w2) {
    __shared__ float s[32][33];
    int k0 = blockIdx.x * 32, j0 = blockIdx.y * 32, i = blockIdx.z;
    int tx = threadIdx.x, ty = threadIdx.y;
#pragma unroll
    for (int r = 0; r < 4; ++r) {
        int kk = ty + r * 8;
        s[kk][tx] = w2[(size_t)(k0 + kk) * HH + i * NH + j0 + tx];
    }
    __syncthreads();
#pragma unroll
    for (int r = 0; r < 4; ++r) {
        int jj = ty + r * 8;
        int m = (j0 + jj) * NH + i;
        g_w2p[(size_t)m * NH + k0 + tx] = tf32r(s[tx][jj]);
    }
}

__global__ void bias_perm(const float* __restrict__ b2) {
    int m = blockIdx.x * blockDim.x + threadIdx.x;
    if (m < HH) g_b2p[m] = b2[(m & 127) * NH + (m >> 7)];
}

__global__ void edge_mlp(const float* __restrict__ ef, const float* __restrict__ w1,
                         const float* __restrict__ b1) {
    int e = blockIdx.x;
    int t = threadIdx.x;  // 128
    __shared__ float efs[NED];
    if (t < NED) efs[t] = ef[e * NED + t];
    __syncthreads();
    float acc = b1[t];
#pragma unroll
    for (int d = 0; d < NED; ++d) acc = fmaf(efs[d], w1[d * NH + t], acc);
    g_hmid[e * NH + t] = tf32r(fmaxf(acc, 0.0f));
}

// ---------------- elementwise / graph kernels ----------------
__global__ void init_node(const int* __restrict__ unit_type, const float* __restrict__ emb) {
    int idx = blockIdx.x * blockDim.x + threadIdx.x;
    if (idx >= NN * NH) return;
    int n = idx >> 7, i = idx & 127;
    g_node[idx] = emb[unit_type[n] * NH + i];
}

__global__ void init_s2s0() {
    int idx = blockIdx.x * blockDim.x + threadIdx.x;
    if (idx < NB * 2 * NH) g_qstar[idx] = 0.0f;
    if (idx < NB * NH) { g_h[idx] = 0.0f; g_c[idx] = 0.0f; }
}

__global__ void zero_update() {
    int idx = blockIdx.x * blockDim.x + threadIdx.x;
    if (idx < NN * NH) g_update[idx] = 0.0f;
}

// per-edge matvec msg[i] = sum_j T'[e][j][i] * x[node_in[e]][j]; scatter-add
__global__ void msg_scatter(const int* __restrict__ node_in, const int* __restrict__ node_out) {
    int e = blockIdx.x;
    int t = threadIdx.x;  // 128
    __shared__ float xs[NH];
    __shared__ float red[4][NH];
    xs[t] = g_node[node_in[e] * NH + t];
    __syncthreads();
    const int q = t >> 5;
    const int i0 = (t & 31) * 4;
    const __half* Te = g_T + (size_t)e * HH;
    float a0 = 0.f, a1 = 0.f, a2 = 0.f, a3 = 0.f;
#pragma unroll 8
    for (int j = q * 32; j < q * 32 + 32; ++j) {
        uint2 raw = *(const uint2*)(Te + (size_t)j * NH + i0);
        float2 p0 = __half22float2(*reinterpret_cast<__half2*>(&raw.x));
        float2 p1 = __half22float2(*reinterpret_cast<__half2*>(&raw.y));
        float xj = xs[j];
        a0 = fmaf(p0.x, xj, a0);
        a1 = fmaf(p0.y, xj, a1);
        a2 = fmaf(p1.x, xj, a2);
        a3 = fmaf(p1.y, xj, a3);
    }
    red[q][i0] = a0; red[q][i0 + 1] = a1; red[q][i0 + 2] = a2; red[q][i0 + 3] = a3;
    __syncthreads();
    float s = red[0][t] + red[1][t] + red[2][t] + red[3][t];
    atomicAdd(&g_update[node_out[e] * NH + t], s);
}

__global__ void gru_gates(const float* __restrict__ bih, const float* __restrict__ bhh) {
    int idx = blockIdx.x * blockDim.x + threadIdx.x;
    if (idx >= NN * NH) return;
    int n = idx >> 7, i = idx & 127;
    const float* gi = g_gi + (size_t)n * 3 * NH;
    const float* gh = g_gh + (size_t)n * 3 * NH;
    float r  = sigm(gi[i] + bih[i] + gh[i] + bhh[i]);
    float z  = sigm(gi[NH + i] + bih[NH + i] + gh[NH + i] + bhh[NH + i]);
    float nn = tanhf(gi[2 * NH + i] + bih[2 * NH + i] + r * (gh[2 * NH + i] + bhh[2 * NH + i]));
    float h  = g_node[idx];
    g_node[idx] = (1.0f - z) * nn + z * h;
}

__global__ void lstm_gates(const float* __restrict__ bih, const float* __restrict__ bhh) {
    int idx = blockIdx.x * blockDim.x + threadIdx.x;
    if (idx >= NB * NH) return;
    int b = idx >> 7, i = idx & 127;
    const float* g1 = g_gl1 + (size_t)b * 4 * NH;
    const float* g2 = g_gl2 + (size_t)b * 4 * NH;
    float gi = g1[i]          + g2[i]          + bih[i]          + bhh[i];
    float gf = g1[NH + i]     + g2[NH + i]     + bih[NH + i]     + bhh[NH + i];
    float gg = g1[2 * NH + i] + g2[2 * NH + i] + bih[2 * NH + i] + bhh[2 * NH + i];
    float go = g1[3 * NH + i] + g2[3 * NH + i] + bih[3 * NH + i] + bhh[3 * NH + i];
    float cc = sigm(gf) * g_c[idx] + sigm(gi) * tanhf(gg);
    float hh = sigm(go) * tanhf(cc);
    g_c[idx] = cc;
    g_h[idx] = hh;
    g_qstar[b * 2 * NH + i] = hh;
}

__global__ void s2s_prod(const int* __restrict__ n2g) {
    int n = blockIdx.x * (blockDim.x >> 5) + (threadIdx.x >> 5);
    int lane = threadIdx.x & 31;
    if (n >= NN) return;
    int g = n2g[n];
    float4 hv = *(const float4*)(g_h + g * NH + lane * 4);
    float4 fv = *(const float4*)(g_node + n * NH + lane * 4);
    float s = hv.x * fv.x + hv.y * fv.y + hv.z * fv.z + hv.w * fv.w;
#pragma unroll
    for (int o = 16; o; o >>= 1) s += __shfl_xor_sync(0xffffffffu, s, o);
    if (lane == 0) g_prod[n] = s;
}

__global__ void s2s_init() {
    int idx = blockIdx.x * blockDim.x + threadIdx.x;
    if (idx < NB * NH) {
        int b = idx >> 7, i = idx & 127;
        g_qstar[b * 2 * NH + NH + i] = 0.0f;
    }
    if (idx < NB) { g_m[idx] = 0u; g_d[idx] = 0.0f; }
}

__global__ void s2s_max(const int* __restrict__ n2g) {
    int n = blockIdx.x * blockDim.x + threadIdx.x;
    if (n >= NN) return;
    atomicMax(&g_m[n2g[n]], fkey(g_prod[n]));
}

__global__ void s2s_expsum(const int* __restrict__ n2g) {
    int n = blockIdx.x * blockDim.x + threadIdx.x;
    if (n >= NN) return;
    int g = n2g[n];
    float e = expf(g_prod[n] - fdekey(g_m[g]));
    g_prod[n] = e;
    atomicAdd(&g_d[g], e);
}

__global__ void s2s_pool(const int* __restrict__ n2g) {
    int n = blockIdx.x;
    int t = threadIdx.x;  // 128
    int g = n2g[n];
    float attn = g_prod[n] / g_d[g];
    atomicAdd(&g_qstar[g * 2 * NH + NH + t], attn * g_node[n * NH + t]);
}

__global__ void copy_out(float* __restrict__ out, int out_size) {
    int idx = blockIdx.x * blockDim.x + threadIdx.x;
    if (idx >= out_size) return;
    if (idx < NB * 2 * NH) out[idx] = g_qstar[idx];
    else if (idx < NB * 2 * NH + NN * NH) out[idx] = g_node[idx - NB * 2 * NH];
}

// ---------------- launch ----------------
extern "C" void kernel_launch(void* const* d_in, const int* in_sizes, int n_in,
                              void* d_out, int out_size) {
    const int*   unit_type    = (const int*)d_in[0];
    const int*   node_in      = (const int*)d_in[1];
    const int*   node_out     = (const int*)d_in[2];
    const int*   node2graph   = (const int*)d_in[3];
    const float* edge_feature = (const float*)d_in[4];
    const float* embedding    = (const float*)d_in[5];
    const float* mlp_w1       = (const float*)d_in[6];
    const float* mlp_b1       = (const float*)d_in[7];
    const float* mlp_w2       = (const float*)d_in[8];
    const float* mlp_b2       = (const float*)d_in[9];
    const float* gru_w_ih     = (const float*)d_in[10];
    const float* gru_w_hh     = (const float*)d_in[11];
    const float* gru_b_ih     = (const float*)d_in[12];
    const float* gru_b_hh     = (const float*)d_in[13];
    const float* lstm_w_ih    = (const float*)d_in[14];
    const float* lstm_w_hh    = (const float*)d_in[15];
    const float* lstm_b_ih    = (const float*)d_in[16];
    const float* lstm_b_hh    = (const float*)d_in[17];
    float* out = (float*)d_out;

    float *p_hmid, *p_w2p, *p_b2p, *p_update, *p_node, *p_gi, *p_gh,
          *p_qstar, *p_h, *p_gl1, *p_gl2,
          *p_upd2, *p_node2, *p_wih2, *p_whh2, *p_lwih2, *p_lwhh2, *p_q2, *p_h2;
    __half* p_T;
    cudaGetSymbolAddress((void**)&p_hmid,   g_hmid);
    cudaGetSymbolAddress((void**)&p_w2p,    g_w2p);
    cudaGetSymbolAddress((void**)&p_b2p,    g_b2p);
    cudaGetSymbolAddress((void**)&p_T,      g_T);
    cudaGetSymbolAddress((void**)&p_update, g_update);
    cudaGetSymbolAddress((void**)&p_node,   g_node);
    cudaGetSymbolAddress((void**)&p_gi,     g_gi);
    cudaGetSymbolAddress((void**)&p_gh,     g_gh);
    cudaGetSymbolAddress((void**)&p_qstar,  g_qstar);
    cudaGetSymbolAddress((void**)&p_h,      g_h);
    cudaGetSymbolAddress((void**)&p_gl1,    g_gl1);
    cudaGetSymbolAddress((void**)&p_gl2,    g_gl2);
    cudaGetSymbolAddress((void**)&p_upd2,   g_upd2);
    cudaGetSymbolAddress((void**)&p_node2,  g_node2);
    cudaGetSymbolAddress((void**)&p_wih2,   g_wih2);
    cudaGetSymbolAddress((void**)&p_whh2,   g_whh2);
    cudaGetSymbolAddress((void**)&p_lwih2,  g_lwih2);
    cudaGetSymbolAddress((void**)&p_lwhh2,  g_lwhh2);
    cudaGetSymbolAddress((void**)&p_q2,     g_q2);
    cudaGetSymbolAddress((void**)&p_h2,     g_h2);

    init_node<<<(NN * NH + 255) / 256, 256>>>(unit_type, embedding);
    init_s2s0<<<(NB * 2 * NH + 255) / 256, 256>>>();
    w2_transpose<<<dim3(4, 4, 128), dim3(32, 8)>>>(mlp_w2);
    bias_perm<<<(HH + 255) / 256, 256>>>(mlp_b2);
    edge_mlp<<<NE, 128>>>(edge_feature, mlp_w1, mlp_b1);

    // weight splits (hi|lo along K)
    split2<<<(3 * NH * NH + 255) / 256, 256>>>(gru_w_ih,  p_wih2,  3 * NH, NH, 0);
    split2<<<(3 * NH * NH + 255) / 256, 256>>>(gru_w_hh,  p_whh2,  3 * NH, NH, 0);
    split2<<<(4 * NH * 2 * NH + 255) / 256, 256>>>(lstm_w_ih, p_lwih2, 4 * NH, 2 * NH, 0);
    split2<<<(4 * NH * NH + 255) / 256, 256>>>(lstm_w_hh, p_lwhh2, 4 * NH, NH, 0);

    // transform = hmid @ w2p^T  (fp16 out, layout [e][j][i])
    gemm_db<<<dim3(HH / 128, NE / 128), 256>>>(p_hmid, p_w2p, nullptr, p_T, p_b2p,
                                               NE, HH, NH);

    for (int l = 0; l < 3; ++l) {
        zero_update<<<(NN * NH + 255) / 256, 256>>>();
        msg_scatter<<<NE, 128>>>(node_in, node_out);
        split2<<<(NN * NH + 255) / 256, 256>>>(p_update, p_upd2,  NN, NH, 1);  // relu fused
        split2<<<(NN * NH + 255) / 256, 256>>>(p_node,   p_node2, NN, NH, 0);
        gemm_db<<<dim3(3, NN / 128), 256>>>(p_upd2,  p_wih2, p_gi, nullptr, nullptr,
                                            NN, 3 * NH, 2 * NH);
        gemm_db<<<dim3(3, NN / 128), 256>>>(p_node2, p_whh2, p_gh, nullptr, nullptr,
                                            NN, 3 * NH, 2 * NH);
        gru_gates<<<(NN * NH + 255) / 256, 256>>>(gru_b_ih, gru_b_hh);
    }

    for (int s = 0; s < 3; ++s) {
        split2<<<(NB * 2 * NH + 255) / 256, 256>>>(p_qstar, p_q2, NB, 2 * NH, 0);
        split2<<<(NB * NH + 255) / 256, 256>>>(p_h, p_h2, NB, NH, 0);
        gemm_db<<<dim3(4, 4), 256>>>(p_q2, p_lwih2, p_gl1, nullptr, nullptr,
                                     NB, 4 * NH, 4 * NH);
        gemm_db<<<dim3(4, 4), 256>>>(p_h2, p_lwhh2, p_gl2, nullptr, nullptr,
                                     NB, 4 * NH, 2 * NH);
        lstm_gates<<<(NB * NH + 255) / 256, 256>>>(lstm_b_ih, lstm_b_hh);
        s2s_prod<<<(NN + 7) / 8, 256>>>(node2graph);
        s2s_init<<<(NB * NH + 255) / 256, 256>>>();
        s2s_max<<<(NN + 255) / 256, 256>>>(node2graph);
        s2s_expsum<<<(NN + 255) / 256, 256>>>(node2graph);
        s2s_pool<<<NN, 128>>>(node2graph);
    }

    copy_out<<<(out_size + 255) / 256, 256>>>(out, out_size);
}

// round 8
// speedup vs baseline: 2.0438x; 1.4174x over previous
#include <cuda_runtime.h>
#include <cuda_fp16.h>
#include <cstdint>
#include <cstdio>

// ---------------- problem constants ----------------
#define NH   128        // hidden
#define NB   512        // graphs
#define NN   8192       // nodes
#define NE   16384      // edges
#define NED  32         // edge dim
#define HH   16384      // H*H
#define RSH  40         // smem row stride in halves (80 B, conflict-free)

// ---------------- device scratch ----------------
__device__ __half g_hmid[NE * NH];                      // fp16
__device__ __half g_w2ph[HH * NH];                      // fp16, [m=j*128+i][k]
__device__ float  g_b2p[HH];
__device__ __half g_T[(size_t)NE * HH];                 // 512 MB, [e][j][i]
__device__ float  g_node[NN * NH];
__device__ __half g_node2h[NN * 2 * NH];                // hi|lo split of node
__device__ __half g_upd2h[NN * 2 * NH];                 // hi|lo split of relu(update)
__device__ float  g_update[NN * NH];
__device__ float  g_gi[NN * 3 * NH];
__device__ float  g_gh[NN * 3 * NH];
__device__ __half g_wih2h[3 * NH * 2 * NH];
__device__ __half g_whh2h[3 * NH * 2 * NH];
__device__ __half g_lw[4 * NH * 6 * NH];                // [512][768] lstm combined
__device__ __half g_xh[NB * 6 * NH];                    // [512][768] lstm input
__device__ float  g_gl[NB * 4 * NH];
__device__ float  g_h[NB * NH];
__device__ float  g_c[NB * NH];
__device__ float  g_qstar[NB * 2 * NH];
__device__ float  g_prod[NN];
__device__ unsigned int g_m[NB];
__device__ float  g_d[NB];

// ---------------- helpers ----------------
__device__ __forceinline__ float sigm(float x) { return 1.0f / (1.0f + expf(-x)); }

__device__ __forceinline__ unsigned int fkey(float f) {
    unsigned int b = __float_as_uint(f);
    return (b & 0x80000000u) ? ~b : (b | 0x80000000u);
}
__device__ __forceinline__ float fdekey(unsigned int k) {
    unsigned int b = (k & 0x80000000u) ? (k & 0x7fffffffu) : ~k;
    return __uint_as_float(b);
}

__device__ __forceinline__ void mma16(float* c, const uint32_t* a, const uint32_t* b) {
    asm volatile(
        "mma.sync.aligned.m16n8k16.row.col.f32.f16.f16.f32 "
        "{%0,%1,%2,%3},{%4,%5,%6,%7},{%8,%9},{%0,%1,%2,%3};"
        : "+f"(c[0]), "+f"(c[1]), "+f"(c[2]), "+f"(c[3])
        : "r"(a[0]), "r"(a[1]), "r"(a[2]), "r"(a[3]), "r"(b[0]), "r"(b[1]));
}

// ---------------- fp16 GEMM, cp.async double-buffered ----------------
// C[M,N] = A[M,K] @ B[N,K]^T (+bias[n]). A,B fp16; accum fp32.
// Writes fp32 (C) or fp16 (Ch). M,N mult of 128; K mult of 32. 256 threads.
__global__ void __launch_bounds__(256, 2)
gemm_h(const __half* __restrict__ A, const __half* __restrict__ B,
       float* __restrict__ C, __half* __restrict__ Ch,
       const float* __restrict__ bias, int M, int N, int K) {
    __shared__ __half As[2][128][RSH];
    __shared__ __half Bs[2][128][RSH];

    const int tid  = threadIdx.x;
    const int warp = tid >> 5, lane = tid & 31;
    const int grp  = lane >> 2, tig = lane & 3;
    const int wm   = warp & 3, wn = warp >> 2;
    const int m0 = blockIdx.y * 128;
    const int n0 = blockIdx.x * 128;

    float c[2][8][4] = {};

    const int ldrow = tid >> 1;            // 0..127
    const int ldc   = (tid & 1) * 16;      // half offset 0 or 16

    auto load_chunk = [&](int buf, int k0) {
#pragma unroll
        for (int p = 0; p < 2; ++p) {
            int hc = ldc + p * 8;          // 8 halves = 16 B
            uint32_t sa = (uint32_t)__cvta_generic_to_shared(&As[buf][ldrow][hc]);
            uint32_t sb = (uint32_t)__cvta_generic_to_shared(&Bs[buf][ldrow][hc]);
            const __half* ga = A + (size_t)(m0 + ldrow) * K + k0 + hc;
            const __half* gb = B + (size_t)(n0 + ldrow) * K + k0 + hc;
            asm volatile("cp.async.cg.shared.global [%0], [%1], 16;" :: "r"(sa), "l"(ga));
            asm volatile("cp.async.cg.shared.global [%0], [%1], 16;" :: "r"(sb), "l"(gb));
        }
        asm volatile("cp.async.commit_group;");
    };

    const int nch = K >> 5;                // 32-wide K chunks
    load_chunk(0, 0);

    for (int ch = 0; ch < nch; ++ch) {
        if (ch + 1 < nch) {
            load_chunk((ch + 1) & 1, (ch + 1) << 5);
            asm volatile("cp.async.wait_group 1;");
        } else {
            asm volatile("cp.async.wait_group 0;");
        }
        __syncthreads();
        const int buf = ch & 1;
#pragma unroll
        for (int kk = 0; kk < 32; kk += 16) {
            uint32_t a[2][4];
            uint32_t b[8][2];
#pragma unroll
            for (int mf = 0; mf < 2; ++mf) {
                int r = wm * 32 + mf * 16 + grp;
                a[mf][0] = *(const uint32_t*)&As[buf][r][kk + 2 * tig];
                a[mf][1] = *(const uint32_t*)&As[buf][r + 8][kk + 2 * tig];
                a[mf][2] = *(const uint32_t*)&As[buf][r][kk + 2 * tig + 8];
                a[mf][3] = *(const uint32_t*)&As[buf][r + 8][kk + 2 * tig + 8];
            }
#pragma unroll
            for (int nf = 0; nf < 8; ++nf) {
                int col = wn * 64 + nf * 8 + grp;
                b[nf][0] = *(const uint32_t*)&Bs[buf][col][kk + 2 * tig];
                b[nf][1] = *(const uint32_t*)&Bs[buf][col][kk + 2 * tig + 8];
            }
#pragma unroll
            for (int mf = 0; mf < 2; ++mf)
#pragma unroll
                for (int nf = 0; nf < 8; ++nf)
                    mma16(c[mf][nf], a[mf], b[nf]);
        }
        __syncthreads();
    }

#pragma unroll
    for (int mf = 0; mf < 2; ++mf) {
        int r0 = m0 + wm * 32 + mf * 16 + grp;
#pragma unroll
        for (int nf = 0; nf < 8; ++nf) {
            int cn = n0 + wn * 64 + nf * 8 + tig * 2;
            float v0 = c[mf][nf][0], v1 = c[mf][nf][1];
            float v2 = c[mf][nf][2], v3 = c[mf][nf][3];
            if (bias) {
                float b0 = bias[cn], b1 = bias[cn + 1];
                v0 += b0; v1 += b1; v2 += b0; v3 += b1;
            }
            if (Ch) {
                *(__half2*)(Ch + (size_t)r0 * N + cn)       = __floats2half2_rn(v0, v1);
                *(__half2*)(Ch + (size_t)(r0 + 8) * N + cn) = __floats2half2_rn(v2, v3);
            } else {
                *(float2*)(C + (size_t)r0 * N + cn)       = make_float2(v0, v1);
                *(float2*)(C + (size_t)(r0 + 8) * N + cn) = make_float2(v2, v3);
            }
        }
    }
}

// ---------------- prep kernels ----------------
// fp16 hi|lo split along K: out[r][c]=hi, out[r][K+c]=lo
__global__ void split2h(const float* __restrict__ in, __half* __restrict__ out,
                        int R, int K, int relu) {
    int idx = blockIdx.x * blockDim.x + threadIdx.x;
    if (idx >= R * K) return;
    int r = idx / K, ccol = idx - r * K;
    float x = in[idx];
    if (relu) x = fmaxf(x, 0.0f);
    __half hi = __float2half_rn(x);
    __half lo = __float2half_rn(x - __half2float(hi));
    out[(size_t)r * 2 * K + ccol]     = hi;
    out[(size_t)r * 2 * K + K + ccol] = lo;
}

// w2 [k][i*128+j] -> g_w2ph [(j*128+i)][k] fp16, coalesced tiles
__global__ void w2_transpose(const float* __restrict__ w2) {
    __shared__ float s[32][33];
    int k0 = blockIdx.x * 32, j0 = blockIdx.y * 32, i = blockIdx.z;
    int tx = threadIdx.x, ty = threadIdx.y;
#pragma unroll
    for (int r = 0; r < 4; ++r) {
        int kk = ty + r * 8;
        s[kk][tx] = w2[(size_t)(k0 + kk) * HH + i * NH + j0 + tx];
    }
    __syncthreads();
#pragma unroll
    for (int r = 0; r < 4; ++r) {
        int jj = ty + r * 8;
        int m = (j0 + jj) * NH + i;
        g_w2ph[(size_t)m * NH + k0 + tx] = __float2half_rn(s[tx][jj]);
    }
}

__global__ void bias_perm(const float* __restrict__ b2) {
    int m = blockIdx.x * blockDim.x + threadIdx.x;
    if (m < HH) g_b2p[m] = b2[(m & 127) * NH + (m >> 7)];
}

__global__ void edge_mlp(const float* __restrict__ ef, const float* __restrict__ w1,
                         const float* __restrict__ b1) {
    int e = blockIdx.x;
    int t = threadIdx.x;  // 128
    __shared__ float efs[NED];
    if (t < NED) efs[t] = ef[e * NED + t];
    __syncthreads();
    float acc = b1[t];
#pragma unroll
    for (int d = 0; d < NED; ++d) acc = fmaf(efs[d], w1[d * NH + t], acc);
    g_hmid[e * NH + t] = __float2half_rn(fmaxf(acc, 0.0f));
}

// lstm combined weight: [4H][768] = [wih_hi | wih_lo | whh_hi | whh_lo]
__global__ void lstm_wprep(const float* __restrict__ wih, const float* __restrict__ whh) {
    int idx = blockIdx.x * blockDim.x + threadIdx.x;
    if (idx >= 4 * NH * 3 * NH) return;          // 512*384
    int r = idx / (3 * NH), ccol = idx - r * (3 * NH);
    float x; int chi, clo;
    if (ccol < 2 * NH) { x = wih[r * 2 * NH + ccol]; chi = ccol;            clo = 2 * NH + ccol; }
    else { int k = ccol - 2 * NH; x = whh[r * NH + k]; chi = 4 * NH + k;    clo = 5 * NH + k; }
    __half hi = __float2half_rn(x);
    __half lo = __float2half_rn(x - __half2float(hi));
    g_lw[(size_t)r * 6 * NH + chi] = hi;
    g_lw[(size_t)r * 6 * NH + clo] = lo;
}

// lstm combined input: [NB][768] from qstar[NB,2H], h[NB,H]
__global__ void lstm_xprep() {
    int idx = blockIdx.x * blockDim.x + threadIdx.x;
    if (idx >= NB * 3 * NH) return;
    int r = idx / (3 * NH), ccol = idx - r * (3 * NH);
    float x; int chi, clo;
    if (ccol < 2 * NH) { x = g_qstar[r * 2 * NH + ccol]; chi = ccol;        clo = 2 * NH + ccol; }
    else { int k = ccol - 2 * NH; x = g_h[r * NH + k];   chi = 4 * NH + k;  clo = 5 * NH + k; }
    __half hi = __float2half_rn(x);
    __half lo = __float2half_rn(x - __half2float(hi));
    g_xh[(size_t)r * 6 * NH + chi] = hi;
    g_xh[(size_t)r * 6 * NH + clo] = lo;
}

// ---------------- elementwise / graph kernels ----------------
__global__ void init_node(const int* __restrict__ unit_type, const float* __restrict__ emb) {
    int idx = blockIdx.x * blockDim.x + threadIdx.x;
    if (idx >= NN * NH) return;
    int n = idx >> 7, i = idx & 127;
    float v = emb[unit_type[n] * NH + i];
    g_node[idx] = v;
    __half hi = __float2half_rn(v);
    g_node2h[(size_t)n * 2 * NH + i]      = hi;
    g_node2h[(size_t)n * 2 * NH + NH + i] = __float2half_rn(v - __half2float(hi));
}

__global__ void init_s2s0() {
    int idx = blockIdx.x * blockDim.x + threadIdx.x;
    if (idx < NB * 2 * NH) g_qstar[idx] = 0.0f;
    if (idx < NB * NH) { g_h[idx] = 0.0f; g_c[idx] = 0.0f; }
}

__global__ void zero_update() {
    int idx = blockIdx.x * blockDim.x + threadIdx.x;
    if (idx < NN * NH) g_update[idx] = 0.0f;
}

// per-edge matvec msg[i] = sum_j T'[e][j][i] * x[node_in[e]][j]; scatter-add
__global__ void msg_scatter(const int* __restrict__ node_in, const int* __restrict__ node_out) {
    int e = blockIdx.x;
    int t = threadIdx.x;  // 128
    __shared__ float xs[NH];
    __shared__ float red[4][NH];
    xs[t] = g_node[node_in[e] * NH + t];
    __syncthreads();
    const int q = t >> 5;
    const int i0 = (t & 31) * 4;
    const __half* Te = g_T + (size_t)e * HH;
    float a0 = 0.f, a1 = 0.f, a2 = 0.f, a3 = 0.f;
#pragma unroll 8
    for (int j = q * 32; j < q * 32 + 32; ++j) {
        uint2 raw = *(const uint2*)(Te + (size_t)j * NH + i0);
        float2 p0 = __half22float2(*reinterpret_cast<__half2*>(&raw.x));
        float2 p1 = __half22float2(*reinterpret_cast<__half2*>(&raw.y));
        float xj = xs[j];
        a0 = fmaf(p0.x, xj, a0);
        a1 = fmaf(p0.y, xj, a1);
        a2 = fmaf(p1.x, xj, a2);
        a3 = fmaf(p1.y, xj, a3);
    }
    red[q][i0] = a0; red[q][i0 + 1] = a1; red[q][i0 + 2] = a2; red[q][i0 + 3] = a3;
    __syncthreads();
    float s = red[0][t] + red[1][t] + red[2][t] + red[3][t];
    atomicAdd(&g_update[node_out[e] * NH + t], s);
}

__global__ void gru_gates(const float* __restrict__ bih, const float* __restrict__ bhh) {
    int idx = blockIdx.x * blockDim.x + threadIdx.x;
    if (idx >= NN * NH) return;
    int n = idx >> 7, i = idx & 127;
    const float* gi = g_gi + (size_t)n * 3 * NH;
    const float* gh = g_gh + (size_t)n * 3 * NH;
    float r  = sigm(gi[i] + bih[i] + gh[i] + bhh[i]);
    float z  = sigm(gi[NH + i] + bih[NH + i] + gh[NH + i] + bhh[NH + i]);
    float nn = tanhf(gi[2 * NH + i] + bih[2 * NH + i] + r * (gh[2 * NH + i] + bhh[2 * NH + i]));
    float h  = g_node[idx];
    float nh = (1.0f - z) * nn + z * h;
    g_node[idx] = nh;
    __half hi = __float2half_rn(nh);
    g_node2h[(size_t)n * 2 * NH + i]      = hi;
    g_node2h[(size_t)n * 2 * NH + NH + i] = __float2half_rn(nh - __half2float(hi));
}

// lstm gates + s2s per-step init (zero pooled qstar, m, d)
__global__ void lstm_gates(const float* __restrict__ bih, const float* __restrict__ bhh) {
    int idx = blockIdx.x * blockDim.x + threadIdx.x;
    if (idx >= NB * NH) return;
    int b = idx >> 7, i = idx & 127;
    const float* g1 = g_gl + (size_t)b * 4 * NH;
    float gi = g1[i]          + bih[i]          + bhh[i];
    float gf = g1[NH + i]     + bih[NH + i]     + bhh[NH + i];
    float gg = g1[2 * NH + i] + bih[2 * NH + i] + bhh[2 * NH + i];
    float go = g1[3 * NH + i] + bih[3 * NH + i] + bhh[3 * NH + i];
    float cc = sigm(gf) * g_c[idx] + sigm(gi) * tanhf(gg);
    float hh = sigm(go) * tanhf(cc);
    g_c[idx] = cc;
    g_h[idx] = hh;
    g_qstar[b * 2 * NH + i]      = hh;
    g_qstar[b * 2 * NH + NH + i] = 0.0f;      // zero pooled part
    if (i == 0) { g_m[b] = 0u; g_d[b] = 0.0f; }
}

__global__ void s2s_prod(const int* __restrict__ n2g) {
    int n = blockIdx.x * (blockDim.x >> 5) + (threadIdx.x >> 5);
    int lane = threadIdx.x & 31;
    if (n >= NN) return;
    int g = n2g[n];
    float4 hv = *(const float4*)(g_h + g * NH + lane * 4);
    float4 fv = *(const float4*)(g_node + n * NH + lane * 4);
    float s = hv.x * fv.x + hv.y * fv.y + hv.z * fv.z + hv.w * fv.w;
#pragma unroll
    for (int o = 16; o; o >>= 1) s += __shfl_xor_sync(0xffffffffu, s, o);
    if (lane == 0) g_prod[n] = s;
}

__global__ void s2s_max(const int* __restrict__ n2g) {
    int n = blockIdx.x * blockDim.x + threadIdx.x;
    if (n >= NN) return;
    atomicMax(&g_m[n2g[n]], fkey(g_prod[n]));
}

__global__ void s2s_expsum(const int* __restrict__ n2g) {
    int n = blockIdx.x * blockDim.x + threadIdx.x;
    if (n >= NN) return;
    int g = n2g[n];
    float e = expf(g_prod[n] - fdekey(g_m[g]));
    g_prod[n] = e;
    atomicAdd(&g_d[g], e);
}

__global__ void s2s_pool(const int* __restrict__ n2g) {
    int n = blockIdx.x;
    int t = threadIdx.x;  // 128
    int g = n2g[n];
    float attn = g_prod[n] / g_d[g];
    atomicAdd(&g_qstar[g * 2 * NH + NH + t], attn * g_node[n * NH + t]);
}

__global__ void copy_out(float* __restrict__ out, int out_size) {
    int idx = blockIdx.x * blockDim.x + threadIdx.x;
    if (idx >= out_size) return;
    if (idx < NB * 2 * NH) out[idx] = g_qstar[idx];
    else if (idx < NB * 2 * NH + NN * NH) out[idx] = g_node[idx - NB * 2 * NH];
}

// ---------------- launch ----------------
extern "C" void kernel_launch(void* const* d_in, const int* in_sizes, int n_in,
                              void* d_out, int out_size) {
    const int*   unit_type    = (const int*)d_in[0];
    const int*   node_in      = (const int*)d_in[1];
    const int*   node_out     = (const int*)d_in[2];
    const int*   node2graph   = (const int*)d_in[3];
    const float* edge_feature = (const float*)d_in[4];
    const float* embedding    = (const float*)d_in[5];
    const float* mlp_w1       = (const float*)d_in[6];
    const float* mlp_b1       = (const float*)d_in[7];
    const float* mlp_w2       = (const float*)d_in[8];
    const float* mlp_b2       = (const float*)d_in[9];
    const float* gru_w_ih     = (const float*)d_in[10];
    const float* gru_w_hh     = (const float*)d_in[11];
    const float* gru_b_ih     = (const float*)d_in[12];
    const float* gru_b_hh     = (const float*)d_in[13];
    const float* lstm_w_ih    = (const float*)d_in[14];
    const float* lstm_w_hh    = (const float*)d_in[15];
    const float* lstm_b_ih    = (const float*)d_in[16];
    const float* lstm_b_hh    = (const float*)d_in[17];
    float* out = (float*)d_out;

    __half *p_hmid, *p_w2ph, *p_T, *p_node2h, *p_upd2h, *p_wih2h, *p_whh2h, *p_lw, *p_xh;
    float *p_b2p, *p_update, *p_gi, *p_gh, *p_gl;
    cudaGetSymbolAddress((void**)&p_hmid,   g_hmid);
    cudaGetSymbolAddress((void**)&p_w2ph,   g_w2ph);
    cudaGetSymbolAddress((void**)&p_b2p,    g_b2p);
    cudaGetSymbolAddress((void**)&p_T,      g_T);
    cudaGetSymbolAddress((void**)&p_update, g_update);
    cudaGetSymbolAddress((void**)&p_node2h, g_node2h);
    cudaGetSymbolAddress((void**)&p_upd2h,  g_upd2h);
    cudaGetSymbolAddress((void**)&p_wih2h,  g_wih2h);
    cudaGetSymbolAddress((void**)&p_whh2h,  g_whh2h);
    cudaGetSymbolAddress((void**)&p_lw,     g_lw);
    cudaGetSymbolAddress((void**)&p_xh,     g_xh);
    cudaGetSymbolAddress((void**)&p_gi,     g_gi);
    cudaGetSymbolAddress((void**)&p_gh,     g_gh);
    cudaGetSymbolAddress((void**)&p_gl,     g_gl);

    // launches 1..3: T-GEMM operand prep
    edge_mlp<<<NE, 128>>>(edge_feature, mlp_w1, mlp_b1);
    w2_transpose<<<dim3(4, 4, 128), dim3(32, 8)>>>(mlp_w2);
    bias_perm<<<(HH + 255) / 256, 256>>>(mlp_b2);

    // launch 4 (profiled by ncu): transform = hmid @ w2ph^T  (fp16 out, [e][j][i])
    gemm_h<<<dim3(HH / 128, NE / 128), 256>>>(p_hmid, p_w2ph, nullptr, p_T, p_b2p,
                                              NE, HH, NH);

    init_node<<<(NN * NH + 255) / 256, 256>>>(unit_type, embedding);
    init_s2s0<<<(NB * 2 * NH + 255) / 256, 256>>>();
    split2h<<<(3 * NH * NH + 255) / 256, 256>>>(gru_w_ih, p_wih2h, 3 * NH, NH, 0);
    split2h<<<(3 * NH * NH + 255) / 256, 256>>>(gru_w_hh, p_whh2h, 3 * NH, NH, 0);
    lstm_wprep<<<(4 * NH * 3 * NH + 255) / 256, 256>>>(lstm_w_ih, lstm_w_hh);

    for (int l = 0; l < 3; ++l) {
        zero_update<<<(NN * NH + 255) / 256, 256>>>();
        msg_scatter<<<NE, 128>>>(node_in, node_out);
        split2h<<<(NN * NH + 255) / 256, 256>>>(p_update, p_upd2h, NN, NH, 1);
        gemm_h<<<dim3(3, NN / 128), 256>>>(p_upd2h,  p_wih2h, p_gi, nullptr, nullptr,
                                           NN, 3 * NH, 2 * NH);
        gemm_h<<<dim3(3, NN / 128), 256>>>(p_node2h, p_whh2h, p_gh, nullptr, nullptr,
                                           NN, 3 * NH, 2 * NH);
        gru_gates<<<(NN * NH + 255) / 256, 256>>>(gru_b_ih, gru_b_hh);
    }

    for (int s = 0; s < 3; ++s) {
        lstm_xprep<<<(NB * 3 * NH + 255) / 256, 256>>>();
        gemm_h<<<dim3(4, 4), 256>>>(p_xh, p_lw, p_gl, nullptr, nullptr,
                                    NB, 4 * NH, 6 * NH);
        lstm_gates<<<(NB * NH + 255) / 256, 256>>>(lstm_b_ih, lstm_b_hh);
        s2s_prod<<<(NN + 7) / 8, 256>>>(node2graph);
        s2s_max<<<(NN + 255) / 256, 256>>>(node2graph);
        s2s_expsum<<<(NN + 255) / 256, 256>>>(node2graph);
        s2s_pool<<<NN, 128>>>(node2graph);
    }

    copy_out<<<(out_size + 255) / 256, 256>>>(out, out_size);
}

// round 13
// speedup vs baseline: 2.0710x; 1.0133x over previous
#include <cuda_runtime.h>
#include <cuda_fp16.h>
#include <cstdint>
#include <cstdio>

// ---------------- problem constants ----------------
#define NH   128        // hidden
#define NB   512        // graphs
#define NN   8192       // nodes
#define NE   16384      // edges
#define NED  32         // edge dim
#define HH   16384      // H*H
#define RSH  40         // gemm_h smem row stride in halves
#define SRS  136        // gemm_T smem row stride in halves (272 B)

// ---------------- device scratch ----------------
__device__ __half g_hmid[NE * NH];                      // fp16
__device__ __half g_w2ph[HH * NH];                      // fp16, [m=j*128+i][k]
__device__ float  g_b2p[HH];
__device__ __half g_T[(size_t)NE * HH];                 // 512 MB, [e][j][i]
__device__ float  g_node[NN * NH];
__device__ __half g_node2h[NN * 2 * NH];                // hi|lo split of node
__device__ __half g_upd2h[NN * 2 * NH];                 // hi|lo split of relu(update)
__device__ float  g_update[NN * NH];
__device__ float  g_gi[NN * 3 * NH];
__device__ float  g_gh[NN * 3 * NH];
__device__ __half g_wih2h[3 * NH * 2 * NH];
__device__ __half g_whh2h[3 * NH * 2 * NH];
__device__ __half g_lw[4 * NH * 6 * NH];                // [512][768] lstm combined
__device__ __half g_xh[NB * 6 * NH];                    // [512][768] lstm input
__device__ float  g_gl[NB * 4 * NH];
__device__ float  g_h[NB * NH];
__device__ float  g_c[NB * NH];
__device__ float  g_qstar[NB * 2 * NH];
__device__ float  g_prod[NN];
__device__ unsigned int g_m[NB];
__device__ float  g_d[NB];

// ---------------- helpers ----------------
__device__ __forceinline__ float sigm(float x) { return 1.0f / (1.0f + expf(-x)); }

__device__ __forceinline__ unsigned int fkey(float f) {
    unsigned int b = __float_as_uint(f);
    return (b & 0x80000000u) ? ~b : (b | 0x80000000u);
}
__device__ __forceinline__ float fdekey(unsigned int k) {
    unsigned int b = (k & 0x80000000u) ? (k & 0x7fffffffu) : ~k;
    return __uint_as_float(b);
}

__device__ __forceinline__ void mma16(float* c, const uint32_t* a, const uint32_t* b) {
    asm volatile(
        "mma.sync.aligned.m16n8k16.row.col.f32.f16.f16.f32 "
        "{%0,%1,%2,%3},{%4,%5,%6,%7},{%8,%9},{%0,%1,%2,%3};"
        : "+f"(c[0]), "+f"(c[1]), "+f"(c[2]), "+f"(c[3])
        : "r"(a[0]), "r"(a[1]), "r"(a[2]), "r"(a[3]), "r"(b[0]), "r"(b[1]));
}

// ---------------- T-GEMM: K=128 fixed, A-resident, 4 B-tiles per CTA ----------------
// T[m][n] fp16 = A[m][0:128] @ B[n][0:128]^T + bias[n], m-tile 128, n-tile 4x128.
__global__ void __launch_bounds__(256, 2)
gemm_T(const __half* __restrict__ A, const __half* __restrict__ B,
       __half* __restrict__ Ch, const float* __restrict__ bias) {
    extern __shared__ __half sm[];
    __half* As  = sm;                       // [128][SRS]
    __half* Bs0 = sm + 128 * SRS;           // [128][SRS]
    __half* Bs1 = sm + 2 * 128 * SRS;

    const int tid  = threadIdx.x;
    const int warp = tid >> 5, lane = tid & 31;
    const int grp  = lane >> 2, tig = lane & 3;
    const int wm   = warp & 3, wn = warp >> 2;
    const int m0 = blockIdx.y * 128;
    const int n0 = blockIdx.x * 512;

    const int ldrow = tid >> 1;
    const int ldcb  = (tid & 1) * 64;

    auto load_tile = [&](__half* dst, const __half* src) {
#pragma unroll
        for (int p = 0; p < 8; ++p) {
            int col = ldcb + p * 8;
            uint32_t s = (uint32_t)__cvta_generic_to_shared(dst + ldrow * SRS + col);
            const __half* g = src + (size_t)ldrow * 128 + col;
            asm volatile("cp.async.cg.shared.global [%0], [%1], 16;" :: "r"(s), "l"(g));
        }
        asm volatile("cp.async.commit_group;");
    };

    load_tile(As, A + (size_t)m0 * 128);
    load_tile(Bs0, B + (size_t)n0 * 128);
    asm volatile("cp.async.wait_group 0;");
    __syncthreads();

    int buf = 0;
    for (int nt = 0; nt < 4; ++nt) {
        if (nt < 3)
            load_tile(buf ? Bs0 : Bs1, B + (size_t)(n0 + (nt + 1) * 128) * 128);

        const __half* Bsc = buf ? Bs1 : Bs0;
        float c[2][8][4] = {};
#pragma unroll
        for (int kk = 0; kk < 128; kk += 16) {
            uint32_t a[2][4];
            uint32_t b[8][2];
#pragma unroll
            for (int mf = 0; mf < 2; ++mf) {
                int r = wm * 32 + mf * 16 + grp;
                a[mf][0] = *(const uint32_t*)&As[r * SRS + kk + 2 * tig];
                a[mf][1] = *(const uint32_t*)&As[(r + 8) * SRS + kk + 2 * tig];
                a[mf][2] = *(const uint32_t*)&As[r * SRS + kk + 2 * tig + 8];
                a[mf][3] = *(const uint32_t*)&As[(r + 8) * SRS + kk + 2 * tig + 8];
            }
#pragma unroll
            for (int nf = 0; nf < 8; ++nf) {
                int col = wn * 64 + nf * 8 + grp;
                b[nf][0] = *(const uint32_t*)&Bsc[col * SRS + kk + 2 * tig];
                b[nf][1] = *(const uint32_t*)&Bsc[col * SRS + kk + 2 * tig + 8];
            }
#pragma unroll
            for (int mf = 0; mf < 2; ++mf)
#pragma unroll
                for (int nf = 0; nf < 8; ++nf)
                    mma16(c[mf][nf], a[mf], b[nf]);
        }

#pragma unroll
        for (int mf = 0; mf < 2; ++mf) {
            int r0 = m0 + wm * 32 + mf * 16 + grp;
#pragma unroll
            for (int nf = 0; nf < 8; ++nf) {
                int cn = n0 + nt * 128 + wn * 64 + nf * 8 + tig * 2;
                float b0 = bias[cn], b1 = bias[cn + 1];
                *(__half2*)(Ch + (size_t)r0 * HH + cn) =
                    __floats2half2_rn(c[mf][nf][0] + b0, c[mf][nf][1] + b1);
                *(__half2*)(Ch + (size_t)(r0 + 8) * HH + cn) =
                    __floats2half2_rn(c[mf][nf][2] + b0, c[mf][nf][3] + b1);
            }
        }

        if (nt < 3) asm volatile("cp.async.wait_group 0;");
        __syncthreads();
        buf ^= 1;
    }
}

// ---------------- generic fp16 GEMM, cp.async double-buffered ----------------
__global__ void __launch_bounds__(256, 2)
gemm_h(const __half* __restrict__ A, const __half* __restrict__ B,
       float* __restrict__ C, const float* __restrict__ bias,
       int M, int N, int K) {
    __shared__ __half As[2][128][RSH];
    __shared__ __half Bs[2][128][RSH];

    const int tid  = threadIdx.x;
    const int warp = tid >> 5, lane = tid & 31;
    const int grp  = lane >> 2, tig = lane & 3;
    const int wm   = warp & 3, wn = warp >> 2;
    const int m0 = blockIdx.y * 128;
    const int n0 = blockIdx.x * 128;

    float c[2][8][4] = {};

    const int ldrow = tid >> 1;
    const int ldc   = (tid & 1) * 16;

    auto load_chunk = [&](int buf, int k0) {
#pragma unroll
        for (int p = 0; p < 2; ++p) {
            int hc = ldc + p * 8;
            uint32_t sa = (uint32_t)__cvta_generic_to_shared(&As[buf][ldrow][hc]);
            uint32_t sb = (uint32_t)__cvta_generic_to_shared(&Bs[buf][ldrow][hc]);
            const __half* ga = A + (size_t)(m0 + ldrow) * K + k0 + hc;
            const __half* gb = B + (size_t)(n0 + ldrow) * K + k0 + hc;
            asm volatile("cp.async.cg.shared.global [%0], [%1], 16;" :: "r"(sa), "l"(ga));
            asm volatile("cp.async.cg.shared.global [%0], [%1], 16;" :: "r"(sb), "l"(gb));
        }
        asm volatile("cp.async.commit_group;");
    };

    const int nch = K >> 5;
    load_chunk(0, 0);

    for (int ch = 0; ch < nch; ++ch) {
        if (ch + 1 < nch) {
            load_chunk((ch + 1) & 1, (ch + 1) << 5);
            asm volatile("cp.async.wait_group 1;");
        } else {
            asm volatile("cp.async.wait_group 0;");
        }
        __syncthreads();
        const int buf = ch & 1;
#pragma unroll
        for (int kk = 0; kk < 32; kk += 16) {
            uint32_t a[2][4];
            uint32_t b[8][2];
#pragma unroll
            for (int mf = 0; mf < 2; ++mf) {
                int r = wm * 32 + mf * 16 + grp;
                a[mf][0] = *(const uint32_t*)&As[buf][r][kk + 2 * tig];
                a[mf][1] = *(const uint32_t*)&As[buf][r + 8][kk + 2 * tig];
                a[mf][2] = *(const uint32_t*)&As[buf][r][kk + 2 * tig + 8];
                a[mf][3] = *(const uint32_t*)&As[buf][r + 8][kk + 2 * tig + 8];
            }
#pragma unroll
            for (int nf = 0; nf < 8; ++nf) {
                int col = wn * 64 + nf * 8 + grp;
                b[nf][0] = *(const uint32_t*)&Bs[buf][col][kk + 2 * tig];
                b[nf][1] = *(const uint32_t*)&Bs[buf][col][kk + 2 * tig + 8];
            }
#pragma unroll
            for (int mf = 0; mf < 2; ++mf)
#pragma unroll
                for (int nf = 0; nf < 8; ++nf)
                    mma16(c[mf][nf], a[mf], b[nf]);
        }
        __syncthreads();
    }

#pragma unroll
    for (int mf = 0; mf < 2; ++mf) {
        int r0 = m0 + wm * 32 + mf * 16 + grp;
#pragma unroll
        for (int nf = 0; nf < 8; ++nf) {
            int cn = n0 + wn * 64 + nf * 8 + tig * 2;
            float v0 = c[mf][nf][0], v1 = c[mf][nf][1];
            float v2 = c[mf][nf][2], v3 = c[mf][nf][3];
            if (bias) {
                float b0 = bias[cn], b1 = bias[cn + 1];
                v0 += b0; v1 += b1; v2 += b0; v3 += b1;
            }
            *(float2*)(C + (size_t)r0 * N + cn)       = make_float2(v0, v1);
            *(float2*)(C + (size_t)(r0 + 8) * N + cn) = make_float2(v2, v3);
        }
    }
}

// ---------------- prep kernels ----------------
__global__ void split2h(const float* __restrict__ in, __half* __restrict__ out,
                        int R, int K, int relu) {
    int idx = blockIdx.x * blockDim.x + threadIdx.x;
    if (idx >= R * K) return;
    int r = idx / K, ccol = idx - r * K;
    float x = in[idx];
    if (relu) x = fmaxf(x, 0.0f);
    __half hi = __float2half_rn(x);
    __half lo = __float2half_rn(x - __half2float(hi));
    out[(size_t)r * 2 * K + ccol]     = hi;
    out[(size_t)r * 2 * K + K + ccol] = lo;
}

__global__ void w2_transpose(const float* __restrict__ w2) {
    __shared__ float s[32][33];
    int k0 = blockIdx.x * 32, j0 = blockIdx.y * 32, i = blockIdx.z;
    int tx = threadIdx.x, ty = threadIdx.y;
#pragma unroll
    for (int r = 0; r < 4; ++r) {
        int kk = ty + r * 8;
        s[kk][tx] = w2[(size_t)(k0 + kk) * HH + i * NH + j0 + tx];
    }
    __syncthreads();
#pragma unroll
    for (int r = 0; r < 4; ++r) {
        int jj = ty + r * 8;
        int m = (j0 + jj) * NH + i;
        g_w2ph[(size_t)m * NH + k0 + tx] = __float2half_rn(s[tx][jj]);
    }
}

__global__ void bias_perm(const float* __restrict__ b2) {
    int m = blockIdx.x * blockDim.x + threadIdx.x;
    if (m < HH) g_b2p[m] = b2[(m & 127) * NH + (m >> 7)];
}

__global__ void edge_mlp(const float* __restrict__ ef, const float* __restrict__ w1,
                         const float* __restrict__ b1) {
    int e = blockIdx.x;
    int t = threadIdx.x;  // 128
    __shared__ float efs[NED];
    if (t < NED) efs[t] = ef[e * NED + t];
    __syncthreads();
    float acc = b1[t];
#pragma unroll
    for (int d = 0; d < NED; ++d) acc = fmaf(efs[d], w1[d * NH + t], acc);
    g_hmid[e * NH + t] = __float2half_rn(fmaxf(acc, 0.0f));
}

__global__ void lstm_wprep(const float* __restrict__ wih, const float* __restrict__ whh) {
    int idx = blockIdx.x * blockDim.x + threadIdx.x;
    if (idx >= 4 * NH * 3 * NH) return;
    int r = idx / (3 * NH), ccol = idx - r * (3 * NH);
    float x; int chi, clo;
    if (ccol < 2 * NH) { x = wih[r * 2 * NH + ccol]; chi = ccol;            clo = 2 * NH + ccol; }
    else { int k = ccol - 2 * NH; x = whh[r * NH + k]; chi = 4 * NH + k;    clo = 5 * NH + k; }
    __half hi = __float2half_rn(x);
    __half lo = __float2half_rn(x - __half2float(hi));
    g_lw[(size_t)r * 6 * NH + chi] = hi;
    g_lw[(size_t)r * 6 * NH + clo] = lo;
}

__global__ void lstm_xprep() {
    int idx = blockIdx.x * blockDim.x + threadIdx.x;
    if (idx >= NB * 3 * NH) return;
    int r = idx / (3 * NH), ccol = idx - r * (3 * NH);
    float x; int chi, clo;
    if (ccol < 2 * NH) { x = g_qstar[r * 2 * NH + ccol]; chi = ccol;        clo = 2 * NH + ccol; }
    else { int k = ccol - 2 * NH; x = g_h[r * NH + k];   chi = 4 * NH + k;  clo = 5 * NH + k; }
    __half hi = __float2half_rn(x);
    __half lo = __float2half_rn(x - __half2float(hi));
    g_xh[(size_t)r * 6 * NH + chi] = hi;
    g_xh[(size_t)r * 6 * NH + clo] = lo;
}

// ---------------- elementwise / graph kernels ----------------
__global__ void init_node(const int* __restrict__ unit_type, const float* __restrict__ emb) {
    int idx = blockIdx.x * blockDim.x + threadIdx.x;
    if (idx >= NN * NH) return;
    int n = idx >> 7, i = idx & 127;
    float v = emb[unit_type[n] * NH + i];
    g_node[idx] = v;
    __half hi = __float2half_rn(v);
    g_node2h[(size_t)n * 2 * NH + i]      = hi;
    g_node2h[(size_t)n * 2 * NH + NH + i] = __float2half_rn(v - __half2float(hi));
}

__global__ void init_s2s0() {
    int idx = blockIdx.x * blockDim.x + threadIdx.x;
    if (idx < NB * 2 * NH) g_qstar[idx] = 0.0f;
    if (idx < NB * NH) { g_h[idx] = 0.0f; g_c[idx] = 0.0f; }
}

__global__ void zero_update() {
    int idx = blockIdx.x * blockDim.x + threadIdx.x;
    if (idx < NN * NH) g_update[idx] = 0.0f;
}

// per-edge matvec msg[i] = sum_j T'[e][j][i] * x[node_in[e]][j]; scatter-add
__global__ void msg_scatter(const int* __restrict__ node_in, const int* __restrict__ node_out) {
    int e = blockIdx.x;
    int t = threadIdx.x;  // 128
    __shared__ float xs[NH];
    __shared__ float red[8][NH];
    xs[t] = g_node[node_in[e] * NH + t];
    __syncthreads();
    const int q  = t >> 4;           // j-group 0..7 (16 j each)
    const int i0 = (t & 15) * 8;     // 8 output columns
    const __half* Te = g_T + (size_t)e * HH;
    float acc[8] = {};
#pragma unroll
    for (int jo = 0; jo < 16; ++jo) {
        int j = q * 16 + jo;
        uint4 raw = *(const uint4*)(Te + (size_t)j * NH + i0);
        float2 p0 = __half22float2(*reinterpret_cast<__half2*>(&raw.x));
        float2 p1 = __half22float2(*reinterpret_cast<__half2*>(&raw.y));
        float2 p2 = __half22float2(*reinterpret_cast<__half2*>(&raw.z));
        float2 p3 = __half22float2(*reinterpret_cast<__half2*>(&raw.w));
        float xj = xs[j];
        acc[0] = fmaf(p0.x, xj, acc[0]);
        acc[1] = fmaf(p0.y, xj, acc[1]);
        acc[2] = fmaf(p1.x, xj, acc[2]);
        acc[3] = fmaf(p1.y, xj, acc[3]);
        acc[4] = fmaf(p2.x, xj, acc[4]);
        acc[5] = fmaf(p2.y, xj, acc[5]);
        acc[6] = fmaf(p3.x, xj, acc[6]);
        acc[7] = fmaf(p3.y, xj, acc[7]);
    }
#pragma unroll
    for (int k = 0; k < 8; ++k) red[q][i0 + k] = acc[k];
    __syncthreads();
    float s = 0.0f;
#pragma unroll
    for (int q2 = 0; q2 < 8; ++q2) s += red[q2][t];
    atomicAdd(&g_update[node_out[e] * NH + t], s);
}

__global__ void gru_gates(const float* __restrict__ bih, const float* __restrict__ bhh) {
    int idx = blockIdx.x * blockDim.x + threadIdx.x;
    if (idx >= NN * NH) return;
    int n = idx >> 7, i = idx & 127;
    const float* gi = g_gi + (size_t)n * 3 * NH;
    const float* gh = g_gh + (size_t)n * 3 * NH;
    float r  = sigm(gi[i] + bih[i] + gh[i] + bhh[i]);
    float z  = sigm(gi[NH + i] + bih[NH + i] + gh[NH + i] + bhh[NH + i]);
    float nn = tanhf(gi[2 * NH + i] + bih[2 * NH + i] + r * (gh[2 * NH + i] + bhh[2 * NH + i]));
    float h  = g_node[idx];
    float nh = (1.0f - z) * nn + z * h;
    g_node[idx] = nh;
    __half hi = __float2half_rn(nh);
    g_node2h[(size_t)n * 2 * NH + i]      = hi;
    g_node2h[(size_t)n * 2 * NH + NH + i] = __float2half_rn(nh - __half2float(hi));
}

__global__ void lstm_gates(const float* __restrict__ bih, const float* __restrict__ bhh) {
    int idx = blockIdx.x * blockDim.x + threadIdx.x;
    if (idx >= NB * NH) return;
    int b = idx >> 7, i = idx & 127;
    const float* g1 = g_gl + (size_t)b * 4 * NH;
    float gi = g1[i]          + bih[i]          + bhh[i];
    float gf = g1[NH + i]     + bih[NH + i]     + bhh[NH + i];
    float gg = g1[2 * NH + i] + bih[2 * NH + i] + bhh[2 * NH + i];
    float go = g1[3 * NH + i] + bih[3 * NH + i] + bhh[3 * NH + i];
    float cc = sigm(gf) * g_c[idx] + sigm(gi) * tanhf(gg);
    float hh = sigm(go) * tanhf(cc);
    g_c[idx] = cc;
    g_h[idx] = hh;
    g_qstar[b * 2 * NH + i]      = hh;
    g_qstar[b * 2 * NH + NH + i] = 0.0f;
    if (i == 0) { g_m[b] = 0u; g_d[b] = 0.0f; }
}

__global__ void s2s_prod(const int* __restrict__ n2g) {
    int n = blockIdx.x * (blockDim.x >> 5) + (threadIdx.x >> 5);
    int lane = threadIdx.x & 31;
    if (n >= NN) return;
    int g = n2g[n];
    float4 hv = *(const float4*)(g_h + g * NH + lane * 4);
    float4 fv = *(const float4*)(g_node + n * NH + lane * 4);
    float s = hv.x * fv.x + hv.y * fv.y + hv.z * fv.z + hv.w * fv.w;
#pragma unroll
    for (int o = 16; o; o >>= 1) s += __shfl_xor_sync(0xffffffffu, s, o);
    if (lane == 0) g_prod[n] = s;
}

__global__ void s2s_max(const int* __restrict__ n2g) {
    int n = blockIdx.x * blockDim.x + threadIdx.x;
    if (n >= NN) return;
    atomicMax(&g_m[n2g[n]], fkey(g_prod[n]));
}

__global__ void s2s_expsum(const int* __restrict__ n2g) {
    int n = blockIdx.x * blockDim.x + threadIdx.x;
    if (n >= NN) return;
    int g = n2g[n];
    float e = expf(g_prod[n] - fdekey(g_m[g]));
    g_prod[n] = e;
    atomicAdd(&g_d[g], e);
}

__global__ void s2s_pool(const int* __restrict__ n2g) {
    int n = blockIdx.x;
    int t = threadIdx.x;  // 128
    int g = n2g[n];
    float attn = g_prod[n] / g_d[g];
    atomicAdd(&g_qstar[g * 2 * NH + NH + t], attn * g_node[n * NH + t]);
}

__global__ void copy_out(float* __restrict__ out, int out_size) {
    int idx = blockIdx.x * blockDim.x + threadIdx.x;
    if (idx >= out_size) return;
    if (idx < NB * 2 * NH) out[idx] = g_qstar[idx];
    else if (idx < NB * 2 * NH + NN * NH) out[idx] = g_node[idx - NB * 2 * NH];
}

// ---------------- launch ----------------
extern "C" void kernel_launch(void* const* d_in, const int* in_sizes, int n_in,
                              void* d_out, int out_size) {
    const int*   unit_type    = (const int*)d_in[0];
    const int*   node_in      = (const int*)d_in[1];
    const int*   node_out     = (const int*)d_in[2];
    const int*   node2graph   = (const int*)d_in[3];
    const float* edge_feature = (const float*)d_in[4];
    const float* embedding    = (const float*)d_in[5];
    const float* mlp_w1       = (const float*)d_in[6];
    const float* mlp_b1       = (const float*)d_in[7];
    const float* mlp_w2       = (const float*)d_in[8];
    const float* mlp_b2       = (const float*)d_in[9];
    const float* gru_w_ih     = (const float*)d_in[10];
    const float* gru_w_hh     = (const float*)d_in[11];
    const float* gru_b_ih     = (const float*)d_in[12];
    const float* gru_b_hh     = (const float*)d_in[13];
    const float* lstm_w_ih    = (const float*)d_in[14];
    const float* lstm_w_hh    = (const float*)d_in[15];
    const float* lstm_b_ih    = (const float*)d_in[16];
    const float* lstm_b_hh    = (const float*)d_in[17];
    float* out = (float*)d_out;

    __half *p_hmid, *p_w2ph, *p_T, *p_node2h, *p_upd2h, *p_wih2h, *p_whh2h, *p_lw, *p_xh;
    float *p_b2p, *p_update, *p_gi, *p_gh, *p_gl;
    cudaGetSymbolAddress((void**)&p_hmid,   g_hmid);
    cudaGetSymbolAddress((void**)&p_w2ph,   g_w2ph);
    cudaGetSymbolAddress((void**)&p_b2p,    g_b2p);
    cudaGetSymbolAddress((void**)&p_T,      g_T);
    cudaGetSymbolAddress((void**)&p_update, g_update);
    cudaGetSymbolAddress((void**)&p_node2h, g_node2h);
    cudaGetSymbolAddress((void**)&p_upd2h,  g_upd2h);
    cudaGetSymbolAddress((void**)&p_wih2h,  g_wih2h);
    cudaGetSymbolAddress((void**)&p_whh2h,  g_whh2h);
    cudaGetSymbolAddress((void**)&p_lw,     g_lw);
    cudaGetSymbolAddress((void**)&p_xh,     g_xh);
    cudaGetSymbolAddress((void**)&p_gi,     g_gi);
    cudaGetSymbolAddress((void**)&p_gh,     g_gh);
    cudaGetSymbolAddress((void**)&p_gl,     g_gl);

    const int SMT = 3 * 128 * SRS * 2;      // 104448 B dynamic smem for gemm_T
    cudaFuncSetAttribute(gemm_T, cudaFuncAttributeMaxDynamicSharedMemorySize, SMT);

    // launches 1..3: T-GEMM operand prep
    edge_mlp<<<NE, 128>>>(edge_feature, mlp_w1, mlp_b1);
    w2_transpose<<<dim3(4, 4, 128), dim3(32, 8)>>>(mlp_w2);
    bias_perm<<<(HH + 255) / 256, 256>>>(mlp_b2);

    // launch 4 (profiled by ncu): transform = hmid @ w2ph^T  (fp16 out, [e][j][i])
    gemm_T<<<dim3(HH / 512, NE / 128), 256, SMT>>>(p_hmid, p_w2ph, p_T, p_b2p);

    init_node<<<(NN * NH + 255) / 256, 256>>>(unit_type, embedding);
    init_s2s0<<<(NB * 2 * NH + 255) / 256, 256>>>();
    split2h<<<(3 * NH * NH + 255) / 256, 256>>>(gru_w_ih, p_wih2h, 3 * NH, NH, 0);
    split2h<<<(3 * NH * NH + 255) / 256, 256>>>(gru_w_hh, p_whh2h, 3 * NH, NH, 0);
    lstm_wprep<<<(4 * NH * 3 * NH + 255) / 256, 256>>>(lstm_w_ih, lstm_w_hh);

    for (int l = 0; l < 3; ++l) {
        zero_update<<<(NN * NH + 255) / 256, 256>>>();
        msg_scatter<<<NE, 128>>>(node_in, node_out);
        split2h<<<(NN * NH + 255) / 256, 256>>>(p_update, p_upd2h, NN, NH, 1);
        gemm_h<<<dim3(3, NN / 128), 256>>>(p_upd2h,  p_wih2h, p_gi, nullptr,
                                           NN, 3 * NH, 2 * NH);
        gemm_h<<<dim3(3, NN / 128), 256>>>(p_node2h, p_whh2h, p_gh, nullptr,
                                           NN, 3 * NH, 2 * NH);
        gru_gates<<<(NN * NH + 255) / 256, 256>>>(gru_b_ih, gru_b_hh);
    }

    for (int s = 0; s < 3; ++s) {
        lstm_xprep<<<(NB * 3 * NH + 255) / 256, 256>>>();
        gemm_h<<<dim3(4, 4), 256>>>(p_xh, p_lw, p_gl, nullptr, NB, 4 * NH, 6 * NH);
        lstm_gates<<<(NB * NH + 255) / 256, 256>>>(lstm_b_ih, lstm_b_hh);
        s2s_prod<<<(NN + 7) / 8, 256>>>(node2graph);
        s2s_max<<<(NN + 255) / 256, 256>>>(node2graph);
        s2s_expsum<<<(NN + 255) / 256, 256>>>(node2graph);
        s2s_pool<<<NN, 128>>>(node2graph);
    }

    copy_out<<<(out_size + 255) / 256, 256>>>(out, out_size);
}